// round 2
// baseline (speedup 1.0000x reference)
#include <cuda_runtime.h>
#include <math.h>

#define BB 4
#define CC 64
#define HH 64
#define WW 64
#define LLEN 4096
#define RR 64
#define DD 128
#define KK 4
#define NN 16
#define NCH 32
#define EPSV 1e-5f
#define BKLD (BB*LLEN*DD)

// ---------------- scratch ----------------
__device__ float g_gamma[BB*CC];
__device__ float g_beta[BB*CC];
__device__ float g_cond[BB*DD];
__device__ float g_att[BB*CC];
__device__ float g_mu[BB*CC];
__device__ float g_rstd[BB*CC];
__device__ float g_WinT[CC*2*DD];
__device__ float g_xc[BB*DD*LLEN];
__device__ float g_zs[BB*LLEN*DD];
__device__ float g_xa[BB*DD*LLEN];
__device__ float g_xaT[BB*DD*LLEN];
__device__ float g_xsb[BB*KK*LLEN*DD];
__device__ float g_dtb[BB*KK*LLEN*DD];
__device__ float g_BC[BB*KK*LLEN*32];
__device__ float g_hend[BB*KK*NCH*NN*DD];
__device__ float g_ap[BB*KK*NCH*NN*DD];
__device__ float g_H0[BB*KK*NCH*NN*DD];
__device__ float g_ysb[KK*BB*LLEN*DD];

// ---------------- K1: small GEMVs + W_in transpose ----------------
__global__ void k_small(const float* rep, const float* Wg, const float* bg,
                        const float* Wb, const float* bb,
                        const float* Wc, const float* bc,
                        const float* Wf1, const float* bf1,
                        const float* Wf2, const float* bf2,
                        const float* Win)
{
    __shared__ float rs[BB*RR];
    __shared__ float a_sm[BB*16];
    int t = threadIdx.x;
    if (t < BB*RR) rs[t] = rep[t];
    __syncthreads();
    {
        int b = t >> 6, c = t & 63;
        float ag = 0.f, ab = 0.f;
        for (int r = 0; r < RR; r++) {
            float rv = rs[b*RR + r];
            ag += rv * Wg[c*RR + r];
            ab += rv * Wb[c*RR + r];
        }
        g_gamma[t] = ag + bg[c];
        g_beta[t]  = ab + bb[c];
    }
    for (int i = t; i < BB*DD; i += 256) {
        int b = i >> 7, d = i & 127;
        float a = 0.f;
        for (int r = 0; r < RR; r++) a += rs[b*RR + r] * Wc[d*RR + r];
        g_cond[i] = 1.0f + a + bc[d];
    }
    if (t < BB*16) {
        int b = t >> 4, j = t & 15;
        float a = 0.f;
        for (int r = 0; r < RR; r++) a += rs[b*RR + r] * Wf1[j*RR + r];
        a += bf1[j];
        a_sm[t] = a > 0.f ? a : 0.f;
    }
    __syncthreads();
    {
        int b = t >> 6, c = t & 63;
        float s = bf2[c];
        for (int j = 0; j < 16; j++) s += a_sm[b*16 + j] * Wf2[c*16 + j];
        g_att[t] = 1.0f / (1.0f + __expf(-s));
    }
    for (int i = t; i < 2*DD*CC; i += 256) {
        int o = i / CC, c = i - o*CC;
        g_WinT[c*(2*DD) + o] = Win[i];
    }
}

// ---------------- K2: instance-norm stats ----------------
__global__ void k_stats(const float* inp)
{
    int bc = blockIdx.x;
    int t = threadIdx.x;
    const float* p = inp + bc*LLEN;
    float s = 0.f, s2 = 0.f;
    for (int i = t; i < LLEN; i += 256) { float v = p[i]; s += v; s2 += v*v; }
    __shared__ float sh[64];
    for (int off = 16; off; off >>= 1) {
        s  += __shfl_xor_sync(0xffffffffu, s,  off);
        s2 += __shfl_xor_sync(0xffffffffu, s2, off);
    }
    int w = t >> 5, lane = t & 31;
    if (lane == 0) { sh[w] = s; sh[32 + w] = s2; }
    __syncthreads();
    if (t == 0) {
        float S = 0.f, S2 = 0.f;
        for (int i = 0; i < 8; i++) { S += sh[i]; S2 += sh[32 + i]; }
        float mu = S / (float)LLEN;
        float var = S2 / (float)LLEN - mu*mu;
        g_mu[bc] = mu;
        g_rstd[bc] = rsqrtf(var + EPSV);
    }
}

// ---------------- K3: FiLM + in-projection GEMM ----------------
__global__ void __launch_bounds__(256) k_inproj(const float* inp)
{
    __shared__ float buf[256*33];   // phase A: [64][36] x tile ; phase B: [256][33] staging
    int bx = blockIdx.x;
    int b  = bx >> 7;
    int l0 = (bx & 127) * 32;
    int t = threadIdx.x;
    // phase A: FiLM'd x tile [c][li], pitch 36
    for (int i = t; i < CC*32; i += 256) {
        int c = i >> 5, li = i & 31;
        int bc = b*CC + c;
        float v  = inp[bc*LLEN + l0 + li];
        float sc = g_rstd[bc] * (1.0f + g_gamma[bc]);
        float bi = g_beta[bc] - g_mu[bc]*sc;
        buf[c*36 + li] = v*sc + bi;
    }
    __syncthreads();
    int o = t;
    float acc[32];
#pragma unroll
    for (int li = 0; li < 32; li++) acc[li] = 0.f;
    for (int c = 0; c < CC; c++) {
        float w = g_WinT[c*256 + o];
        const float4* xp = (const float4*)&buf[c*36];
#pragma unroll
        for (int q = 0; q < 8; q++) {
            float4 x4 = xp[q];
            acc[q*4+0] += w*x4.x; acc[q*4+1] += w*x4.y;
            acc[q*4+2] += w*x4.z; acc[q*4+3] += w*x4.w;
        }
    }
    if (o >= DD) {
#pragma unroll
        for (int li = 0; li < 32; li++) {
            float z = acc[li];
            acc[li] = z / (1.0f + __expf(-z));   // silu(z)
        }
    }
    __syncthreads();
#pragma unroll
    for (int li = 0; li < 32; li++) buf[o*33 + li] = acc[li];
    __syncthreads();
    for (int i = t; i < DD*32; i += 256) {        // xc -> (b,d,l)
        int d = i >> 5, li = i & 31;
        g_xc[(b*DD + d)*LLEN + l0 + li] = buf[d*33 + li];
    }
    for (int i = t; i < DD*32; i += 256) {        // silu(z) -> (b,l,d)
        int li = i >> 7, zd = i & 127;
        g_zs[(b*LLEN + l0 + li)*DD + zd] = buf[(128 + zd)*33 + li];
    }
}

// ---------------- K4: depthwise 3x3 conv + silu (+ transpose) ----------------
__global__ void __launch_bounds__(256) k_conv(const float* cw, const float* cb)
{
    int bd = blockIdx.x;
    int d = bd & 127;
    __shared__ float insm[66*66];
    __shared__ float osm[64*65];
    int t = threadIdx.x;
    for (int i = t; i < 66*66; i += 256) insm[i] = 0.f;
    __syncthreads();
    const float* src = &g_xc[bd*LLEN];
    for (int i = t; i < LLEN; i += 256) {
        int h = i >> 6, w = i & 63;
        insm[(h+1)*66 + (w+1)] = src[i];
    }
    float wv[9];
#pragma unroll
    for (int i = 0; i < 9; i++) wv[i] = cw[d*9 + i];
    float bias = cb[d];
    __syncthreads();
    float* dsta = &g_xa[bd*LLEN];
    for (int i = t; i < LLEN; i += 256) {
        int h = i >> 6, w = i & 63;
        float a = bias;
#pragma unroll
        for (int ki = 0; ki < 3; ki++)
#pragma unroll
            for (int kj = 0; kj < 3; kj++)
                a += insm[(h+ki)*66 + (w+kj)] * wv[ki*3+kj];
        float v = a / (1.0f + __expf(-a));
        dsta[i] = v;
        osm[h*65 + w] = v;
    }
    __syncthreads();
    float* dstt = &g_xaT[bd*LLEN];
    for (int i = t; i < LLEN; i += 256) {
        int h = i & 63, w = i >> 6;     // i = w*64 + h
        dstt[i] = osm[h*65 + w];
    }
}

// ---------------- K5: x_dbl + dt projection + layout staging ----------------
__global__ void __launch_bounds__(128) k_xdbl(const float* xpw, const float* dtw, const float* dtbp)
{
    __shared__ float xsT[32*132];
    __shared__ float Wp[36*128];
    __shared__ float xdbl[36*33];
    int bx = blockIdx.x;
    int b  = bx >> 9;
    int k  = (bx >> 7) & 3;
    int lt = bx & 127;
    int bk = b*KK + k;
    int l0 = lt*32;
    int t = threadIdx.x;
    for (int i = t; i < 36*128; i += 128) Wp[i] = xpw[k*36*128 + i];
    const float* src = (k & 1) ? &g_xaT[b*DD*LLEN] : &g_xa[b*DD*LLEN];
    bool flip = (k >= 2);
    for (int i = t; i < DD*32; i += 128) {
        int d = i >> 5, li = i & 31;
        int l = l0 + li;
        int m = flip ? (LLEN - 1 - l) : l;
        xsT[li*132 + d] = src[d*LLEN + m];
    }
    __syncthreads();
    for (int i = t; i < DD*32; i += 128) {   // xs -> (bk,l,d)
        int li = i >> 7, d = i & 127;
        g_xsb[(bk*LLEN + l0 + li)*DD + d] = xsT[li*132 + d];
    }
    {
        int g = t >> 5, li = t & 31;
        float acc[9];
#pragma unroll
        for (int r = 0; r < 9; r++) acc[r] = 0.f;
        const float4* xp = (const float4*)&xsT[li*132];
        for (int d4 = 0; d4 < 32; d4++) {
            float4 x4 = xp[d4];
#pragma unroll
            for (int r = 0; r < 9; r++) {
                float4 w4 = *(const float4*)&Wp[(g*9 + r)*128 + d4*4];
                acc[r] += x4.x*w4.x + x4.y*w4.y + x4.z*w4.z + x4.w*w4.w;
            }
        }
#pragma unroll
        for (int r = 0; r < 9; r++) xdbl[(g*9 + r)*33 + li] = acc[r];
    }
    __syncthreads();
    {   // dt projection + softplus -> (bk,l,d)
        int d = t;
        float4 w4 = *(const float4*)&dtw[(k*DD + d)*4];
        float bsv = dtbp[k*DD + d];
#pragma unroll 4
        for (int li = 0; li < 32; li++) {
            float s = bsv + xdbl[0*33+li]*w4.x + xdbl[1*33+li]*w4.y
                          + xdbl[2*33+li]*w4.z + xdbl[3*33+li]*w4.w;
            float dt = (s > 20.f) ? s : log1pf(__expf(s));
            g_dtb[(bk*LLEN + l0 + li)*DD + d] = dt;
        }
    }
    for (int i = t; i < 32*32; i += 128) {  // B|C -> (bk,l,32)
        int li = i >> 5, j = i & 31;
        g_BC[(bk*LLEN + l0 + li)*32 + j] = xdbl[(4 + j)*33 + li];
    }
}

// ---------------- K6: scan phase A (per-chunk local scan) ----------------
__global__ void __launch_bounds__(128) k_scanA(const float* Alogs)
{
    int bk = blockIdx.x >> 5;
    int ch = blockIdx.x & 31;
    int k = bk & 3;
    int d = threadIdx.x;
    float a[NN];
    bool fast = true;
#pragma unroll
    for (int n = 0; n < NN; n++) {
        a[n] = -__expf(Alogs[(k*DD + d)*NN + n]);
        fast = fast && (fabsf(a[n] + (float)(n+1)) < 1e-3f);
    }
    float h[NN];
#pragma unroll
    for (int n = 0; n < NN; n++) h[n] = 0.f;
    float S = 0.f;
    int base = bk*LLEN + ch*128;
    if (fast) {
#pragma unroll 2
        for (int s = 0; s < 128; s++) {
            int l = base + s;
            float dt = g_dtb[l*DD + d];
            float x  = g_xsb[l*DD + d];
            float4 bv[4];
            bv[0] = *(const float4*)&g_BC[l*32 +  0];
            bv[1] = *(const float4*)&g_BC[l*32 +  4];
            bv[2] = *(const float4*)&g_BC[l*32 +  8];
            bv[3] = *(const float4*)&g_BC[l*32 + 12];
            const float* bb = (const float*)bv;
            float u = dt*x;
            S += dt;
            float r = __expf(-dt);
            float p = r;
#pragma unroll
            for (int n = 0; n < NN; n++) { h[n] = h[n]*p + u*bb[n]; p *= r; }
        }
    } else {
        for (int s = 0; s < 128; s++) {
            int l = base + s;
            float dt = g_dtb[l*DD + d];
            float x  = g_xsb[l*DD + d];
            float4 bv[4];
            bv[0] = *(const float4*)&g_BC[l*32 +  0];
            bv[1] = *(const float4*)&g_BC[l*32 +  4];
            bv[2] = *(const float4*)&g_BC[l*32 +  8];
            bv[3] = *(const float4*)&g_BC[l*32 + 12];
            const float* bb = (const float*)bv;
            float u = dt*x;
            S += dt;
#pragma unroll
            for (int n = 0; n < NN; n++) h[n] = h[n]*__expf(dt*a[n]) + u*bb[n];
        }
    }
    int cb = bk*NCH + ch;
#pragma unroll
    for (int n = 0; n < NN; n++) {
        g_hend[(cb*NN + n)*DD + d] = h[n];
        g_ap[(cb*NN + n)*DD + d] = __expf(a[n]*S);
    }
}

// ---------------- K7: scan phase B (cross-chunk prefix) ----------------
__global__ void __launch_bounds__(128) k_scanB()
{
    int bk = blockIdx.x;
    int d = threadIdx.x;
    float Hv[NN];
#pragma unroll
    for (int n = 0; n < NN; n++) Hv[n] = 0.f;
    for (int ch = 0; ch < NCH; ch++) {
        int cb = bk*NCH + ch;
#pragma unroll
        for (int n = 0; n < NN; n++) {
            g_H0[(cb*NN + n)*DD + d] = Hv[n];
            Hv[n] = Hv[n]*g_ap[(cb*NN + n)*DD + d] + g_hend[(cb*NN + n)*DD + d];
        }
    }
}

// ---------------- K8: scan phase C (rescan + y + direction scatter) ----------
__global__ void __launch_bounds__(128) k_scanC(const float* Alogs, const float* Ds)
{
    int bk = blockIdx.x >> 5;
    int ch = blockIdx.x & 31;
    int k = bk & 3;
    int b = bk >> 2;
    int d = threadIdx.x;
    float a[NN];
    bool fast = true;
#pragma unroll
    for (int n = 0; n < NN; n++) {
        a[n] = -__expf(Alogs[(k*DD + d)*NN + n]);
        fast = fast && (fabsf(a[n] + (float)(n+1)) < 1e-3f);
    }
    float h[NN];
    int cb = bk*NCH + ch;
#pragma unroll
    for (int n = 0; n < NN; n++) h[n] = g_H0[(cb*NN + n)*DD + d];
    float Dv = Ds[k*DD + d];
    int base = bk*LLEN + ch*128;
    float* dst = &g_ysb[k*BKLD + b*LLEN*DD];
#pragma unroll 2
    for (int s = 0; s < 128; s++) {
        int l = base + s;
        float dt = g_dtb[l*DD + d];
        float x  = g_xsb[l*DD + d];
        float4 bv[4], cv[4];
        bv[0] = *(const float4*)&g_BC[l*32 +  0];
        bv[1] = *(const float4*)&g_BC[l*32 +  4];
        bv[2] = *(const float4*)&g_BC[l*32 +  8];
        bv[3] = *(const float4*)&g_BC[l*32 + 12];
        cv[0] = *(const float4*)&g_BC[l*32 + 16];
        cv[1] = *(const float4*)&g_BC[l*32 + 20];
        cv[2] = *(const float4*)&g_BC[l*32 + 24];
        cv[3] = *(const float4*)&g_BC[l*32 + 28];
        const float* bb = (const float*)bv;
        const float* cc = (const float*)cv;
        float u = dt*x;
        float y = 0.f;
        if (fast) {
            float r = __expf(-dt);
            float p = r;
#pragma unroll
            for (int n = 0; n < NN; n++) { h[n] = h[n]*p + u*bb[n]; y += h[n]*cc[n]; p *= r; }
        } else {
#pragma unroll
            for (int n = 0; n < NN; n++) { h[n] = h[n]*__expf(dt*a[n]) + u*bb[n]; y += h[n]*cc[n]; }
        }
        float ys = y + x*Dv;
        int sa = ch*128 + s;
        int lrow;
        if (k == 0)      lrow = sa;
        else if (k == 1) lrow = ((sa & 63) << 6) | (sa >> 6);
        else if (k == 2) lrow = LLEN - 1 - sa;
        else { int m = LLEN - 1 - sa; lrow = ((m & 63) << 6) | (m >> 6); }
        dst[lrow*DD + d] = ys;
    }
}

// ---------------- K9: combine + LN + gates + out-proj + residual -------------
__global__ void __launch_bounds__(256) k_final(const float* inp, const float* lnw,
                                               const float* lnb, const float* Wout,
                                               float* out)
{
    __shared__ float Wsm[64*132];
    __shared__ float val_sm[8*128];
    __shared__ float osm[64*8];
    int t = threadIdx.x;
    int b = blockIdx.x >> 9;
    int l0 = (blockIdx.x & 511) * 8;
    for (int i = t; i < 64*128; i += 256) {
        int c = i >> 7, dd = i & 127;
        Wsm[c*132 + dd] = Wout[i];
    }
    __syncthreads();
    int w = t >> 5, lane = t & 31;
    int l = l0 + w;
    int off = (b*LLEN + l)*DD + lane*4;
    float4 y4;
    {
        float4 a0 = *(const float4*)&g_ysb[0*BKLD + off];
        float4 a1 = *(const float4*)&g_ysb[1*BKLD + off];
        float4 a2 = *(const float4*)&g_ysb[2*BKLD + off];
        float4 a3 = *(const float4*)&g_ysb[3*BKLD + off];
        y4.x = a0.x + a1.x + a2.x + a3.x;
        y4.y = a0.y + a1.y + a2.y + a3.y;
        y4.z = a0.z + a1.z + a2.z + a3.z;
        y4.w = a0.w + a1.w + a2.w + a3.w;
    }
    float s1 = y4.x + y4.y + y4.z + y4.w;
    float s2 = y4.x*y4.x + y4.y*y4.y + y4.z*y4.z + y4.w*y4.w;
    for (int o2 = 16; o2; o2 >>= 1) {
        s1 += __shfl_xor_sync(0xffffffffu, s1, o2);
        s2 += __shfl_xor_sync(0xffffffffu, s2, o2);
    }
    float mean = s1 * (1.f/128.f);
    float var  = s2 * (1.f/128.f) - mean*mean;
    float rstd = rsqrtf(var + EPSV);
    float4 lw = ((const float4*)lnw)[lane];
    float4 lb = ((const float4*)lnb)[lane];
    float4 cd = *(const float4*)&g_cond[b*DD + lane*4];
    float4 z4 = *(const float4*)&g_zs[off];
    float4 v4;
    v4.x = ((y4.x - mean)*rstd*lw.x + lb.x) * cd.x * z4.x;
    v4.y = ((y4.y - mean)*rstd*lw.y + lb.y) * cd.y * z4.y;
    v4.z = ((y4.z - mean)*rstd*lw.z + lb.z) * cd.z * z4.z;
    v4.w = ((y4.w - mean)*rstd*lw.w + lb.w) * cd.w * z4.w;
    *(float4*)&val_sm[w*128 + lane*4] = v4;
    __syncwarp();
    float acc0 = 0.f, acc1 = 0.f;
    const float4* vp = (const float4*)&val_sm[w*128];
    const float4* w0 = (const float4*)&Wsm[lane*132];
    const float4* w1 = (const float4*)&Wsm[(lane+32)*132];
#pragma unroll 8
    for (int q = 0; q < 32; q++) {
        float4 v = vp[q];
        float4 wa = w0[q];
        float4 wb = w1[q];
        acc0 += v.x*wa.x + v.y*wa.y + v.z*wa.z + v.w*wa.w;
        acc1 += v.x*wb.x + v.y*wb.y + v.z*wb.z + v.w*wb.w;
    }
    osm[lane*8 + w] = acc0;
    osm[(lane+32)*8 + w] = acc1;
    __syncthreads();
    for (int i = t; i < 64*8; i += 256) {
        int c = i >> 3, li = i & 7;
        int gi = (b*CC + c)*LLEN + l0 + li;
        out[gi] = osm[c*8 + li] + inp[gi]*g_att[b*CC + c];
    }
}

extern "C" void kernel_launch(void* const* d_in, const int* in_sizes, int n_in,
                              void* d_out, int out_size)
{
    const float* inp   = (const float*)d_in[0];
    const float* rep   = (const float*)d_in[1];
    const float* Wg    = (const float*)d_in[2];
    const float* bg    = (const float*)d_in[3];
    const float* Wb    = (const float*)d_in[4];
    const float* bbp   = (const float*)d_in[5];
    const float* Win   = (const float*)d_in[6];
    const float* cw    = (const float*)d_in[7];
    const float* cb    = (const float*)d_in[8];
    const float* xpw   = (const float*)d_in[9];
    const float* dtw   = (const float*)d_in[10];
    const float* dtbp  = (const float*)d_in[11];
    const float* Alogs = (const float*)d_in[12];
    const float* Ds    = (const float*)d_in[13];
    const float* lnw   = (const float*)d_in[14];
    const float* lnb   = (const float*)d_in[15];
    const float* Wc    = (const float*)d_in[16];
    const float* bc    = (const float*)d_in[17];
    const float* Wout  = (const float*)d_in[18];
    const float* Wf1   = (const float*)d_in[19];
    const float* bf1   = (const float*)d_in[20];
    const float* Wf2   = (const float*)d_in[21];
    const float* bf2   = (const float*)d_in[22];
    float* out = (float*)d_out;

    k_small<<<1, 256>>>(rep, Wg, bg, Wb, bbp, Wc, bc, Wf1, bf1, Wf2, bf2, Win);
    k_stats<<<BB*CC, 256>>>(inp);
    k_inproj<<<BB*128, 256>>>(inp);
    k_conv<<<BB*DD, 256>>>(cw, cb);
    k_xdbl<<<BB*KK*128, 128>>>(xpw, dtw, dtbp);
    k_scanA<<<BB*KK*NCH, 128>>>(Alogs);
    k_scanB<<<BB*KK, 128>>>();
    k_scanC<<<BB*KK*NCH, 128>>>(Alogs, Ds);
    k_final<<<BB*512, 256>>>(inp, lnw, lnb, Wout, out);
}

// round 3
// speedup vs baseline: 1.4976x; 1.4976x over previous
#include <cuda_runtime.h>
#include <math.h>

#define BB 4
#define CC 64
#define HH 64
#define WW 64
#define LLEN 4096
#define RR 64
#define DD 128
#define KK 4
#define NN 16
#define NCH 64
#define CHL 64
#define EPSV 1e-5f
#define BKLD (BB*LLEN*DD)

// ---------------- scratch ----------------
__device__ float g_gamma[BB*CC];
__device__ float g_beta[BB*CC];
__device__ float g_cond[BB*DD];
__device__ float g_att[BB*CC];
__device__ float g_mu[BB*CC];
__device__ float g_rstd[BB*CC];
__device__ float g_WinT[CC*2*DD];
__device__ float g_xc[BB*DD*LLEN];
__device__ float g_zs[BB*LLEN*DD];
__device__ float g_xa[BB*DD*LLEN];
__device__ float g_xaT[BB*DD*LLEN];
__device__ float g_xsb[BB*2*LLEN*DD];      // only k=0,1 stored; k>=2 is a flip
__device__ float g_dtb[BB*KK*LLEN*DD];
__device__ float g_BC[BB*KK*LLEN*32];
__device__ float g_hend[BB*KK*NCH*NN*DD];
__device__ float g_ap[BB*KK*NCH*NN*DD];
__device__ float g_H0[BB*KK*NCH*NN*DD];
__device__ float g_ysb[KK*BB*LLEN*DD];

// r^1..r^16 with dependency depth ~4
__device__ __forceinline__ void pow_tree(float r, float* p) {
    float r2 = r*r, r4 = r2*r2, r8 = r4*r4;
    p[0]=r;      p[1]=r2;     p[2]=r2*r;    p[3]=r4;
    p[4]=r4*r;   p[5]=r4*r2;  p[6]=r4*p[2]; p[7]=r8;
    p[8]=r8*r;   p[9]=r8*r2;  p[10]=r8*p[2]; p[11]=r8*r4;
    p[12]=r8*p[4]; p[13]=r8*p[5]; p[14]=r8*p[6]; p[15]=r8*r8;
}

// ---------------- K1: small GEMVs + W_in transpose ----------------
__global__ void k_small(const float* rep, const float* Wg, const float* bg,
                        const float* Wb, const float* bb,
                        const float* Wc, const float* bc,
                        const float* Wf1, const float* bf1,
                        const float* Wf2, const float* bf2,
                        const float* Win)
{
    __shared__ float rs[BB*RR];
    __shared__ float a_sm[BB*16];
    int t = threadIdx.x;
    if (t < BB*RR) rs[t] = rep[t];
    __syncthreads();
    {
        int b = t >> 6, c = t & 63;
        float ag = 0.f, ab = 0.f;
        for (int r = 0; r < RR; r++) {
            float rv = rs[b*RR + r];
            ag += rv * Wg[c*RR + r];
            ab += rv * Wb[c*RR + r];
        }
        g_gamma[t] = ag + bg[c];
        g_beta[t]  = ab + bb[c];
    }
    for (int i = t; i < BB*DD; i += 256) {
        int b = i >> 7, d = i & 127;
        float a = 0.f;
        for (int r = 0; r < RR; r++) a += rs[b*RR + r] * Wc[d*RR + r];
        g_cond[i] = 1.0f + a + bc[d];
    }
    if (t < BB*16) {
        int b = t >> 4, j = t & 15;
        float a = 0.f;
        for (int r = 0; r < RR; r++) a += rs[b*RR + r] * Wf1[j*RR + r];
        a += bf1[j];
        a_sm[t] = a > 0.f ? a : 0.f;
    }
    __syncthreads();
    {
        int b = t >> 6, c = t & 63;
        float s = bf2[c];
        for (int j = 0; j < 16; j++) s += a_sm[b*16 + j] * Wf2[c*16 + j];
        g_att[t] = 1.0f / (1.0f + __expf(-s));
    }
    for (int i = t; i < 2*DD*CC; i += 256) {
        int o = i / CC, c = i - o*CC;
        g_WinT[c*(2*DD) + o] = Win[i];
    }
}

// ---------------- K2: instance-norm stats ----------------
__global__ void k_stats(const float* inp)
{
    int bc = blockIdx.x;
    int t = threadIdx.x;
    const float* p = inp + bc*LLEN;
    float s = 0.f, s2 = 0.f;
    for (int i = t; i < LLEN; i += 256) { float v = p[i]; s += v; s2 += v*v; }
    __shared__ float sh[64];
    for (int off = 16; off; off >>= 1) {
        s  += __shfl_xor_sync(0xffffffffu, s,  off);
        s2 += __shfl_xor_sync(0xffffffffu, s2, off);
    }
    int w = t >> 5, lane = t & 31;
    if (lane == 0) { sh[w] = s; sh[32 + w] = s2; }
    __syncthreads();
    if (t == 0) {
        float S = 0.f, S2 = 0.f;
        for (int i = 0; i < 8; i++) { S += sh[i]; S2 += sh[32 + i]; }
        float mu = S / (float)LLEN;
        float var = S2 / (float)LLEN - mu*mu;
        g_mu[bc] = mu;
        g_rstd[bc] = rsqrtf(var + EPSV);
    }
}

// ---------------- K3: FiLM + in-projection GEMM ----------------
__global__ void __launch_bounds__(256) k_inproj(const float* inp)
{
    __shared__ float buf[256*33];
    int bx = blockIdx.x;
    int b  = bx >> 7;
    int l0 = (bx & 127) * 32;
    int t = threadIdx.x;
    for (int i = t; i < CC*32; i += 256) {
        int c = i >> 5, li = i & 31;
        int bc = b*CC + c;
        float v  = inp[bc*LLEN + l0 + li];
        float sc = g_rstd[bc] * (1.0f + g_gamma[bc]);
        float bi = g_beta[bc] - g_mu[bc]*sc;
        buf[c*36 + li] = v*sc + bi;
    }
    __syncthreads();
    int o = t;
    float acc[32];
#pragma unroll
    for (int li = 0; li < 32; li++) acc[li] = 0.f;
    for (int c = 0; c < CC; c++) {
        float w = g_WinT[c*256 + o];
        const float4* xp = (const float4*)&buf[c*36];
#pragma unroll
        for (int q = 0; q < 8; q++) {
            float4 x4 = xp[q];
            acc[q*4+0] += w*x4.x; acc[q*4+1] += w*x4.y;
            acc[q*4+2] += w*x4.z; acc[q*4+3] += w*x4.w;
        }
    }
    if (o >= DD) {
#pragma unroll
        for (int li = 0; li < 32; li++) {
            float z = acc[li];
            acc[li] = z / (1.0f + __expf(-z));
        }
    }
    __syncthreads();
#pragma unroll
    for (int li = 0; li < 32; li++) buf[o*33 + li] = acc[li];
    __syncthreads();
    for (int i = t; i < DD*32; i += 256) {
        int d = i >> 5, li = i & 31;
        g_xc[(b*DD + d)*LLEN + l0 + li] = buf[d*33 + li];
    }
    for (int i = t; i < DD*32; i += 256) {
        int li = i >> 7, zd = i & 127;
        g_zs[(b*LLEN + l0 + li)*DD + zd] = buf[(128 + zd)*33 + li];
    }
}

// ---------------- K4: depthwise 3x3 conv + silu (+ transpose) ----------------
__global__ void __launch_bounds__(256) k_conv(const float* cw, const float* cb)
{
    int bd = blockIdx.x;
    int d = bd & 127;
    __shared__ float insm[66*66];
    __shared__ float osm[64*65];
    int t = threadIdx.x;
    for (int i = t; i < 66*66; i += 256) insm[i] = 0.f;
    __syncthreads();
    const float* src = &g_xc[bd*LLEN];
    for (int i = t; i < LLEN; i += 256) {
        int h = i >> 6, w = i & 63;
        insm[(h+1)*66 + (w+1)] = src[i];
    }
    float wv[9];
#pragma unroll
    for (int i = 0; i < 9; i++) wv[i] = cw[d*9 + i];
    float bias = cb[d];
    __syncthreads();
    float* dsta = &g_xa[bd*LLEN];
    for (int i = t; i < LLEN; i += 256) {
        int h = i >> 6, w = i & 63;
        float a = bias;
#pragma unroll
        for (int ki = 0; ki < 3; ki++)
#pragma unroll
            for (int kj = 0; kj < 3; kj++)
                a += insm[(h+ki)*66 + (w+kj)] * wv[ki*3+kj];
        float v = a / (1.0f + __expf(-a));
        dsta[i] = v;
        osm[h*65 + w] = v;
    }
    __syncthreads();
    float* dstt = &g_xaT[bd*LLEN];
    for (int i = t; i < LLEN; i += 256) {
        int h = i & 63, w = i >> 6;
        dstt[i] = osm[h*65 + w];
    }
}

// ---------------- K5: x_dbl + dt projection + layout staging ----------------
__global__ void __launch_bounds__(128) k_xdbl(const float* xpw, const float* dtw, const float* dtbp)
{
    __shared__ float xsT[32*132];
    __shared__ float Wp[36*128];
    __shared__ float xdbl[36*33];
    int bx = blockIdx.x;
    int b  = bx >> 9;
    int k  = (bx >> 7) & 3;
    int lt = bx & 127;
    int bk = b*KK + k;
    int l0 = lt*32;
    int t = threadIdx.x;
    for (int i = t; i < 36*128; i += 128) Wp[i] = xpw[k*36*128 + i];
    const float* src = (k & 1) ? &g_xaT[b*DD*LLEN] : &g_xa[b*DD*LLEN];
    bool flip = (k >= 2);
    for (int i = t; i < DD*32; i += 128) {
        int d = i >> 5, li = i & 31;
        int l = l0 + li;
        int m = flip ? (LLEN - 1 - l) : l;
        xsT[li*132 + d] = src[d*LLEN + m];
    }
    __syncthreads();
    if (k < 2) {
        int bk2 = b*2 + k;
        for (int i = t; i < DD*32; i += 128) {
            int li = i >> 7, d = i & 127;
            g_xsb[(bk2*LLEN + l0 + li)*DD + d] = xsT[li*132 + d];
        }
    }
    {
        int g = t >> 5, li = t & 31;
        float acc[9];
#pragma unroll
        for (int r = 0; r < 9; r++) acc[r] = 0.f;
        const float4* xp = (const float4*)&xsT[li*132];
        for (int d4 = 0; d4 < 32; d4++) {
            float4 x4 = xp[d4];
#pragma unroll
            for (int r = 0; r < 9; r++) {
                float4 w4 = *(const float4*)&Wp[(g*9 + r)*128 + d4*4];
                acc[r] += x4.x*w4.x + x4.y*w4.y + x4.z*w4.z + x4.w*w4.w;
            }
        }
#pragma unroll
        for (int r = 0; r < 9; r++) xdbl[(g*9 + r)*33 + li] = acc[r];
    }
    __syncthreads();
    {
        int d = t;
        float4 w4 = *(const float4*)&dtw[(k*DD + d)*4];
        float bsv = dtbp[k*DD + d];
#pragma unroll 4
        for (int li = 0; li < 32; li++) {
            float s = bsv + xdbl[0*33+li]*w4.x + xdbl[1*33+li]*w4.y
                          + xdbl[2*33+li]*w4.z + xdbl[3*33+li]*w4.w;
            float dt = (s > 20.f) ? s : log1pf(__expf(s));
            g_dtb[(bk*LLEN + l0 + li)*DD + d] = dt;
        }
    }
    for (int i = t; i < 32*32; i += 128) {
        int li = i >> 5, j = i & 31;
        g_BC[(bk*LLEN + l0 + li)*32 + j] = xdbl[(4 + j)*33 + li];
    }
}

// ---------------- K6: scan phase A (per-chunk local scan) ----------------
__global__ void __launch_bounds__(128) k_scanA(const float* Alogs)
{
    __shared__ float smBC[CHL*32];
    int bk = blockIdx.x >> 6;
    int ch = blockIdx.x & 63;
    int k = bk & 3;
    int b = bk >> 2;
    int d = threadIdx.x;
    int base = ch*CHL;
    // stage B|C for this chunk (coalesced float4)
    {
        const float4* src4 = (const float4*)&g_BC[(bk*LLEN + base)*32];
        float4* dst4 = (float4*)smBC;
        for (int i = d; i < CHL*8; i += 128) dst4[i] = src4[i];
    }
    float a[NN];
    bool fast = true;
#pragma unroll
    for (int n = 0; n < NN; n++) {
        a[n] = -__expf(Alogs[(k*DD + d)*NN + n]);
        fast = fast && (fabsf(a[n] + (float)(n+1)) < 1e-3f);
    }
    float h[NN];
#pragma unroll
    for (int n = 0; n < NN; n++) h[n] = 0.f;
    float S = 0.f;
    const float* dtp = &g_dtb[(bk*LLEN + base)*DD + d];
    int xrow = (b*2 + (k & 1))*LLEN;
    bool flip = (k >= 2);
    __syncthreads();
    if (fast) {
#pragma unroll 2
        for (int s = 0; s < CHL; s++) {
            int l = base + s;
            int lx = flip ? (LLEN - 1 - l) : l;
            float dt = dtp[s*DD];
            float x  = g_xsb[(xrow + lx)*DD + d];
            float u = dt*x;
            S += dt;
            float r = __expf(-dt);
            float p[NN];
            pow_tree(r, p);
            const float* bb = &smBC[s*32];
#pragma unroll
            for (int n = 0; n < NN; n++) h[n] = h[n]*p[n] + u*bb[n];
        }
    } else {
        for (int s = 0; s < CHL; s++) {
            int l = base + s;
            int lx = flip ? (LLEN - 1 - l) : l;
            float dt = dtp[s*DD];
            float x  = g_xsb[(xrow + lx)*DD + d];
            float u = dt*x;
            S += dt;
            const float* bb = &smBC[s*32];
#pragma unroll
            for (int n = 0; n < NN; n++) h[n] = h[n]*__expf(dt*a[n]) + u*bb[n];
        }
    }
    int cb = bk*NCH + ch;
    if (fast) {
        float q = __expf(-S);
        float p[NN];
        pow_tree(q, p);
#pragma unroll
        for (int n = 0; n < NN; n++) {
            g_hend[(cb*NN + n)*DD + d] = h[n];
            g_ap[(cb*NN + n)*DD + d] = p[n];
        }
    } else {
#pragma unroll
        for (int n = 0; n < NN; n++) {
            g_hend[(cb*NN + n)*DD + d] = h[n];
            g_ap[(cb*NN + n)*DD + d] = __expf(a[n]*S);
        }
    }
}

// ---------------- K7: scan phase B (cross-chunk prefix, parallel over n) -----
__global__ void __launch_bounds__(128) k_scanB()
{
    int bk = blockIdx.x >> 4;
    int n  = blockIdx.x & 15;
    int d = threadIdx.x;
    float Hv = 0.f;
    int idx = ((bk*NCH)*NN + n)*DD + d;
    float ap0 = g_ap[idx];
    float he0 = g_hend[idx];
    for (int ch = 0; ch < NCH; ch++) {
        int nidx = idx + NN*DD;
        float ap1 = 0.f, he1 = 0.f;
        if (ch + 1 < NCH) { ap1 = g_ap[nidx]; he1 = g_hend[nidx]; }
        g_H0[idx] = Hv;
        Hv = Hv*ap0 + he0;
        ap0 = ap1; he0 = he1;
        idx = nidx;
    }
}

// ---------------- K8: scan phase C (rescan + y + direction scatter) ----------
__global__ void __launch_bounds__(128) k_scanC(const float* Alogs, const float* Ds)
{
    __shared__ float smBC[CHL*32];
    int bk = blockIdx.x >> 6;
    int ch = blockIdx.x & 63;
    int k = bk & 3;
    int b = bk >> 2;
    int d = threadIdx.x;
    int base = ch*CHL;
    {
        const float4* src4 = (const float4*)&g_BC[(bk*LLEN + base)*32];
        float4* dst4 = (float4*)smBC;
        for (int i = d; i < CHL*8; i += 128) dst4[i] = src4[i];
    }
    float a[NN];
    bool fast = true;
#pragma unroll
    for (int n = 0; n < NN; n++) {
        a[n] = -__expf(Alogs[(k*DD + d)*NN + n]);
        fast = fast && (fabsf(a[n] + (float)(n+1)) < 1e-3f);
    }
    float h[NN];
    int cb = bk*NCH + ch;
#pragma unroll
    for (int n = 0; n < NN; n++) h[n] = g_H0[(cb*NN + n)*DD + d];
    float Dv = Ds[k*DD + d];
    const float* dtp = &g_dtb[(bk*LLEN + base)*DD + d];
    int xrow = (b*2 + (k & 1))*LLEN;
    bool flip = (k >= 2);
    float* dst = &g_ysb[k*BKLD + b*LLEN*DD];
    __syncthreads();
#pragma unroll 2
    for (int s = 0; s < CHL; s++) {
        int l = base + s;
        int lx = flip ? (LLEN - 1 - l) : l;
        float dt = dtp[s*DD];
        float x  = g_xsb[(xrow + lx)*DD + d];
        float u = dt*x;
        const float* bb = &smBC[s*32];
        const float* cc = &smBC[s*32 + 16];
        float y0 = 0.f, y1 = 0.f, y2 = 0.f, y3 = 0.f;
        if (fast) {
            float r = __expf(-dt);
            float p[NN];
            pow_tree(r, p);
#pragma unroll
            for (int n = 0; n < NN; n += 4) {
                h[n+0] = h[n+0]*p[n+0] + u*bb[n+0]; y0 += h[n+0]*cc[n+0];
                h[n+1] = h[n+1]*p[n+1] + u*bb[n+1]; y1 += h[n+1]*cc[n+1];
                h[n+2] = h[n+2]*p[n+2] + u*bb[n+2]; y2 += h[n+2]*cc[n+2];
                h[n+3] = h[n+3]*p[n+3] + u*bb[n+3]; y3 += h[n+3]*cc[n+3];
            }
        } else {
#pragma unroll
            for (int n = 0; n < NN; n += 4) {
                h[n+0] = h[n+0]*__expf(dt*a[n+0]) + u*bb[n+0]; y0 += h[n+0]*cc[n+0];
                h[n+1] = h[n+1]*__expf(dt*a[n+1]) + u*bb[n+1]; y1 += h[n+1]*cc[n+1];
                h[n+2] = h[n+2]*__expf(dt*a[n+2]) + u*bb[n+2]; y2 += h[n+2]*cc[n+2];
                h[n+3] = h[n+3]*__expf(dt*a[n+3]) + u*bb[n+3]; y3 += h[n+3]*cc[n+3];
            }
        }
        float ys = (y0 + y1) + (y2 + y3) + x*Dv;
        int sa = l;
        int lrow;
        if (k == 0)      lrow = sa;
        else if (k == 1) lrow = ((sa & 63) << 6) | (sa >> 6);
        else if (k == 2) lrow = LLEN - 1 - sa;
        else { int m = LLEN - 1 - sa; lrow = ((m & 63) << 6) | (m >> 6); }
        dst[lrow*DD + d] = ys;
    }
}

// ---------------- K9: combine + LN + gates + out-proj + residual -------------
__global__ void __launch_bounds__(256) k_final(const float* inp, const float* lnw,
                                               const float* lnb, const float* Wout,
                                               float* out)
{
    __shared__ float Wsm[64*132];
    __shared__ float val_sm[8*128];
    __shared__ float osm[64*8];
    int t = threadIdx.x;
    int b = blockIdx.x >> 9;
    int l0 = (blockIdx.x & 511) * 8;
    for (int i = t; i < 64*128; i += 256) {
        int c = i >> 7, dd = i & 127;
        Wsm[c*132 + dd] = Wout[i];
    }
    __syncthreads();
    int w = t >> 5, lane = t & 31;
    int l = l0 + w;
    int off = (b*LLEN + l)*DD + lane*4;
    float4 y4;
    {
        float4 a0 = *(const float4*)&g_ysb[0*BKLD + off];
        float4 a1 = *(const float4*)&g_ysb[1*BKLD + off];
        float4 a2 = *(const float4*)&g_ysb[2*BKLD + off];
        float4 a3 = *(const float4*)&g_ysb[3*BKLD + off];
        y4.x = a0.x + a1.x + a2.x + a3.x;
        y4.y = a0.y + a1.y + a2.y + a3.y;
        y4.z = a0.z + a1.z + a2.z + a3.z;
        y4.w = a0.w + a1.w + a2.w + a3.w;
    }
    float s1 = y4.x + y4.y + y4.z + y4.w;
    float s2 = y4.x*y4.x + y4.y*y4.y + y4.z*y4.z + y4.w*y4.w;
    for (int o2 = 16; o2; o2 >>= 1) {
        s1 += __shfl_xor_sync(0xffffffffu, s1, o2);
        s2 += __shfl_xor_sync(0xffffffffu, s2, o2);
    }
    float mean = s1 * (1.f/128.f);
    float var  = s2 * (1.f/128.f) - mean*mean;
    float rstd = rsqrtf(var + EPSV);
    float4 lw = ((const float4*)lnw)[lane];
    float4 lb = ((const float4*)lnb)[lane];
    float4 cd = *(const float4*)&g_cond[b*DD + lane*4];
    float4 z4 = *(const float4*)&g_zs[off];
    float4 v4;
    v4.x = ((y4.x - mean)*rstd*lw.x + lb.x) * cd.x * z4.x;
    v4.y = ((y4.y - mean)*rstd*lw.y + lb.y) * cd.y * z4.y;
    v4.z = ((y4.z - mean)*rstd*lw.z + lb.z) * cd.z * z4.z;
    v4.w = ((y4.w - mean)*rstd*lw.w + lb.w) * cd.w * z4.w;
    *(float4*)&val_sm[w*128 + lane*4] = v4;
    __syncwarp();
    float acc0 = 0.f, acc1 = 0.f;
    const float4* vp = (const float4*)&val_sm[w*128];
    const float4* w0 = (const float4*)&Wsm[lane*132];
    const float4* w1 = (const float4*)&Wsm[(lane+32)*132];
#pragma unroll 8
    for (int q = 0; q < 32; q++) {
        float4 v = vp[q];
        float4 wa = w0[q];
        float4 wb = w1[q];
        acc0 += v.x*wa.x + v.y*wa.y + v.z*wa.z + v.w*wa.w;
        acc1 += v.x*wb.x + v.y*wb.y + v.z*wb.z + v.w*wb.w;
    }
    osm[lane*8 + w] = acc0;
    osm[(lane+32)*8 + w] = acc1;
    __syncthreads();
    for (int i = t; i < 64*8; i += 256) {
        int c = i >> 3, li = i & 7;
        int gi = (b*CC + c)*LLEN + l0 + li;
        out[gi] = osm[c*8 + li] + inp[gi]*g_att[b*CC + c];
    }
}

extern "C" void kernel_launch(void* const* d_in, const int* in_sizes, int n_in,
                              void* d_out, int out_size)
{
    const float* inp   = (const float*)d_in[0];
    const float* rep   = (const float*)d_in[1];
    const float* Wg    = (const float*)d_in[2];
    const float* bg    = (const float*)d_in[3];
    const float* Wb    = (const float*)d_in[4];
    const float* bbp   = (const float*)d_in[5];
    const float* Win   = (const float*)d_in[6];
    const float* cw    = (const float*)d_in[7];
    const float* cb    = (const float*)d_in[8];
    const float* xpw   = (const float*)d_in[9];
    const float* dtw   = (const float*)d_in[10];
    const float* dtbp  = (const float*)d_in[11];
    const float* Alogs = (const float*)d_in[12];
    const float* Ds    = (const float*)d_in[13];
    const float* lnw   = (const float*)d_in[14];
    const float* lnb   = (const float*)d_in[15];
    const float* Wc    = (const float*)d_in[16];
    const float* bc    = (const float*)d_in[17];
    const float* Wout  = (const float*)d_in[18];
    const float* Wf1   = (const float*)d_in[19];
    const float* bf1   = (const float*)d_in[20];
    const float* Wf2   = (const float*)d_in[21];
    const float* bf2   = (const float*)d_in[22];
    float* out = (float*)d_out;

    k_small<<<1, 256>>>(rep, Wg, bg, Wb, bbp, Wc, bc, Wf1, bf1, Wf2, bf2, Win);
    k_stats<<<BB*CC, 256>>>(inp);
    k_inproj<<<BB*128, 256>>>(inp);
    k_conv<<<BB*DD, 256>>>(cw, cb);
    k_xdbl<<<BB*KK*128, 128>>>(xpw, dtw, dtbp);
    k_scanA<<<BB*KK*NCH, 128>>>(Alogs);
    k_scanB<<<BB*KK*NN, 128>>>();
    k_scanC<<<BB*KK*NCH, 128>>>(Alogs, Ds);
    k_final<<<BB*512, 256>>>(inp, lnw, lnb, Wout, out);
}

// round 4
// speedup vs baseline: 1.5536x; 1.0374x over previous
#include <cuda_runtime.h>
#include <math.h>

#define BB 4
#define CC 64
#define HH 64
#define WW 64
#define LLEN 4096
#define RR 64
#define DD 128
#define KK 4
#define NN 16
#define NCH 64
#define CHL 64
#define EPSV 1e-5f
#define BKLD (BB*LLEN*DD)

typedef unsigned long long u64;
typedef unsigned int u32;

__device__ __forceinline__ u64 pk2(float lo, float hi) {
    u64 r; u32 a = __float_as_uint(lo), b = __float_as_uint(hi);
    asm("mov.b64 %0, {%1, %2};" : "=l"(r) : "r"(a), "r"(b));
    return r;
}
__device__ __forceinline__ u64 fma2(u64 a, u64 b, u64 c) {
    u64 d; asm("fma.rn.f32x2 %0, %1, %2, %3;" : "=l"(d) : "l"(a), "l"(b), "l"(c));
    return d;
}
__device__ __forceinline__ u64 mul2(u64 a, u64 b) {
    u64 d; asm("mul.rn.f32x2 %0, %1, %2;" : "=l"(d) : "l"(a), "l"(b));
    return d;
}
__device__ __forceinline__ void upk2(u64 v, float& lo, float& hi) {
    u32 a, b; asm("mov.b64 {%0, %1}, %2;" : "=r"(a), "=r"(b) : "l"(v));
    lo = __uint_as_float(a); hi = __uint_as_float(b);
}
// p2[j] = {r^(2j+1), r^(2j+2)}, dependency depth ~4
__device__ __forceinline__ void pow_tree2(float r, u64* p2) {
    float r2 = r*r, r4 = r2*r2, r8 = r4*r4;
    u64 q0 = pk2(r, r2), s2 = pk2(r2, r2), s4 = pk2(r4, r4), s8 = pk2(r8, r8);
    p2[0] = q0;
    p2[1] = mul2(q0, s2);
    p2[2] = mul2(q0, s4);
    p2[3] = mul2(p2[1], s4);
    p2[4] = mul2(q0, s8);
    p2[5] = mul2(p2[1], s8);
    p2[6] = mul2(p2[2], s8);
    p2[7] = mul2(p2[3], s8);
}

// ---------------- scratch ----------------
__device__ float g_gamma[BB*CC];
__device__ float g_beta[BB*CC];
__device__ float g_cond[BB*DD];
__device__ float g_att[BB*CC];
__device__ float g_mu[BB*CC];
__device__ float g_rstd[BB*CC];
__device__ float g_WinT[CC*2*DD];
__device__ float g_xc[BB*DD*LLEN];
__device__ float g_zs[BB*LLEN*DD];
__device__ float g_xa[BB*DD*LLEN];
__device__ float g_xaT[BB*DD*LLEN];
__device__ float g_xsb[BB*2*LLEN*DD];      // only k=0,1 stored; k>=2 is a flip
__device__ float g_dtb[BB*KK*LLEN*DD];
__device__ float g_BC[BB*KK*LLEN*32];
__device__ float g_hend[BB*KK*NCH*NN*DD];
__device__ float g_ap[BB*KK*NCH*NN*DD];
__device__ float g_H0[BB*KK*NCH*NN*DD];
__device__ float g_ysb[KK*BB*LLEN*DD];

// ---------------- K1: small GEMVs + W_in transpose + IN stats ----------------
__global__ void k_small(const float* rep, const float* Wg, const float* bg,
                        const float* Wb, const float* bb,
                        const float* Wc, const float* bc,
                        const float* Wf1, const float* bf1,
                        const float* Wf2, const float* bf2,
                        const float* Win, const float* inp)
{
    if (blockIdx.x > 0) {       // instance-norm stats, one block per (b,c)
        int bc_i = blockIdx.x - 1;
        int t = threadIdx.x;
        const float* p = inp + bc_i*LLEN;
        float s = 0.f, s2 = 0.f;
        for (int i = t; i < LLEN; i += 256) { float v = p[i]; s += v; s2 += v*v; }
        __shared__ float sh[64];
        for (int off = 16; off; off >>= 1) {
            s  += __shfl_xor_sync(0xffffffffu, s,  off);
            s2 += __shfl_xor_sync(0xffffffffu, s2, off);
        }
        int w = t >> 5, lane = t & 31;
        if (lane == 0) { sh[w] = s; sh[32 + w] = s2; }
        __syncthreads();
        if (t == 0) {
            float S = 0.f, S2 = 0.f;
            for (int i = 0; i < 8; i++) { S += sh[i]; S2 += sh[32 + i]; }
            float mu = S / (float)LLEN;
            float var = S2 / (float)LLEN - mu*mu;
            g_mu[bc_i] = mu;
            g_rstd[bc_i] = rsqrtf(var + EPSV);
        }
        return;
    }
    __shared__ float rs[BB*RR];
    __shared__ float a_sm[BB*16];
    int t = threadIdx.x;
    if (t < BB*RR) rs[t] = rep[t];
    __syncthreads();
    {
        int b = t >> 6, c = t & 63;
        float ag = 0.f, ab = 0.f;
        for (int r = 0; r < RR; r++) {
            float rv = rs[b*RR + r];
            ag += rv * Wg[c*RR + r];
            ab += rv * Wb[c*RR + r];
        }
        g_gamma[t] = ag + bg[c];
        g_beta[t]  = ab + bb[c];
    }
    for (int i = t; i < BB*DD; i += 256) {
        int b = i >> 7, d = i & 127;
        float a = 0.f;
        for (int r = 0; r < RR; r++) a += rs[b*RR + r] * Wc[d*RR + r];
        g_cond[i] = 1.0f + a + bc[d];
    }
    if (t < BB*16) {
        int b = t >> 4, j = t & 15;
        float a = 0.f;
        for (int r = 0; r < RR; r++) a += rs[b*RR + r] * Wf1[j*RR + r];
        a += bf1[j];
        a_sm[t] = a > 0.f ? a : 0.f;
    }
    __syncthreads();
    {
        int b = t >> 6, c = t & 63;
        float s = bf2[c];
        for (int j = 0; j < 16; j++) s += a_sm[b*16 + j] * Wf2[c*16 + j];
        g_att[t] = 1.0f / (1.0f + __expf(-s));
    }
    for (int i = t; i < 2*DD*CC; i += 256) {
        int o = i / CC, c = i - o*CC;
        g_WinT[c*(2*DD) + o] = Win[i];
    }
}

// ---------------- K3: FiLM + in-projection GEMM ----------------
__global__ void __launch_bounds__(256) k_inproj(const float* inp)
{
    __shared__ float buf[256*33];
    int bx = blockIdx.x;
    int b  = bx >> 7;
    int l0 = (bx & 127) * 32;
    int t = threadIdx.x;
    for (int i = t; i < CC*32; i += 256) {
        int c = i >> 5, li = i & 31;
        int bc = b*CC + c;
        float v  = inp[bc*LLEN + l0 + li];
        float sc = g_rstd[bc] * (1.0f + g_gamma[bc]);
        float bi = g_beta[bc] - g_mu[bc]*sc;
        buf[c*36 + li] = v*sc + bi;
    }
    __syncthreads();
    int o = t;
    float acc[32];
#pragma unroll
    for (int li = 0; li < 32; li++) acc[li] = 0.f;
    for (int c = 0; c < CC; c++) {
        float w = g_WinT[c*256 + o];
        const float4* xp = (const float4*)&buf[c*36];
#pragma unroll
        for (int q = 0; q < 8; q++) {
            float4 x4 = xp[q];
            acc[q*4+0] += w*x4.x; acc[q*4+1] += w*x4.y;
            acc[q*4+2] += w*x4.z; acc[q*4+3] += w*x4.w;
        }
    }
    if (o >= DD) {
#pragma unroll
        for (int li = 0; li < 32; li++) {
            float z = acc[li];
            acc[li] = z / (1.0f + __expf(-z));
        }
    }
    __syncthreads();
#pragma unroll
    for (int li = 0; li < 32; li++) buf[o*33 + li] = acc[li];
    __syncthreads();
    for (int i = t; i < DD*32; i += 256) {
        int d = i >> 5, li = i & 31;
        g_xc[(b*DD + d)*LLEN + l0 + li] = buf[d*33 + li];
    }
    for (int i = t; i < DD*32; i += 256) {
        int li = i >> 7, zd = i & 127;
        g_zs[(b*LLEN + l0 + li)*DD + zd] = buf[(128 + zd)*33 + li];
    }
}

// ---------------- K4: depthwise 3x3 conv + silu (+ transpose) ----------------
__global__ void __launch_bounds__(256) k_conv(const float* cw, const float* cb)
{
    int bd = blockIdx.x;
    int d = bd & 127;
    __shared__ float insm[66*66];
    __shared__ float osm[64*65];
    int t = threadIdx.x;
    for (int i = t; i < 66*66; i += 256) insm[i] = 0.f;
    __syncthreads();
    const float* src = &g_xc[bd*LLEN];
    for (int i = t; i < LLEN; i += 256) {
        int h = i >> 6, w = i & 63;
        insm[(h+1)*66 + (w+1)] = src[i];
    }
    float wv[9];
#pragma unroll
    for (int i = 0; i < 9; i++) wv[i] = cw[d*9 + i];
    float bias = cb[d];
    __syncthreads();
    float* dsta = &g_xa[bd*LLEN];
    for (int i = t; i < LLEN; i += 256) {
        int h = i >> 6, w = i & 63;
        float a = bias;
#pragma unroll
        for (int ki = 0; ki < 3; ki++)
#pragma unroll
            for (int kj = 0; kj < 3; kj++)
                a += insm[(h+ki)*66 + (w+kj)] * wv[ki*3+kj];
        float v = a / (1.0f + __expf(-a));
        dsta[i] = v;
        osm[h*65 + w] = v;
    }
    __syncthreads();
    float* dstt = &g_xaT[bd*LLEN];
    for (int i = t; i < LLEN; i += 256) {
        int h = i & 63, w = i >> 6;
        dstt[i] = osm[h*65 + w];
    }
}

// ---------------- K5: x_dbl + dt projection + layout staging ----------------
__global__ void __launch_bounds__(128) k_xdbl(const float* xpw, const float* dtw, const float* dtbp)
{
    __shared__ float xsT[32*132];
    __shared__ float Wp[36*128];
    __shared__ float xdbl[36*33];
    int bx = blockIdx.x;
    int b  = bx >> 9;
    int k  = (bx >> 7) & 3;
    int lt = bx & 127;
    int bk = b*KK + k;
    int l0 = lt*32;
    int t = threadIdx.x;
    for (int i = t; i < 36*128; i += 128) Wp[i] = xpw[k*36*128 + i];
    const float* src = (k & 1) ? &g_xaT[b*DD*LLEN] : &g_xa[b*DD*LLEN];
    bool flip = (k >= 2);
    for (int i = t; i < DD*32; i += 128) {
        int d = i >> 5, li = i & 31;
        int l = l0 + li;
        int m = flip ? (LLEN - 1 - l) : l;
        xsT[li*132 + d] = src[d*LLEN + m];
    }
    __syncthreads();
    if (k < 2) {
        int bk2 = b*2 + k;
        for (int i = t; i < DD*32; i += 128) {
            int li = i >> 7, d = i & 127;
            g_xsb[(bk2*LLEN + l0 + li)*DD + d] = xsT[li*132 + d];
        }
    }
    {
        int g = t >> 5, li = t & 31;
        float acc[9];
#pragma unroll
        for (int r = 0; r < 9; r++) acc[r] = 0.f;
        const float4* xp = (const float4*)&xsT[li*132];
        for (int d4 = 0; d4 < 32; d4++) {
            float4 x4 = xp[d4];
#pragma unroll
            for (int r = 0; r < 9; r++) {
                float4 w4 = *(const float4*)&Wp[(g*9 + r)*128 + d4*4];
                acc[r] += x4.x*w4.x + x4.y*w4.y + x4.z*w4.z + x4.w*w4.w;
            }
        }
#pragma unroll
        for (int r = 0; r < 9; r++) xdbl[(g*9 + r)*33 + li] = acc[r];
    }
    __syncthreads();
    {
        int d = t;
        float4 w4 = *(const float4*)&dtw[(k*DD + d)*4];
        float bsv = dtbp[k*DD + d];
#pragma unroll 4
        for (int li = 0; li < 32; li++) {
            float s = bsv + xdbl[0*33+li]*w4.x + xdbl[1*33+li]*w4.y
                          + xdbl[2*33+li]*w4.z + xdbl[3*33+li]*w4.w;
            float dt = (s > 20.f) ? s : log1pf(__expf(s));
            g_dtb[(bk*LLEN + l0 + li)*DD + d] = dt;
        }
    }
    for (int i = t; i < 32*32; i += 128) {
        int li = i >> 5, j = i & 31;
        g_BC[(bk*LLEN + l0 + li)*32 + j] = xdbl[(4 + j)*33 + li];
    }
}

// ---------------- K6: scan phase A (per-chunk local scan, packed f32x2) ------
__global__ void __launch_bounds__(128) k_scanA(const float* Alogs)
{
    __shared__ float smBC[CHL*32];
    int bk = blockIdx.x >> 6;
    int ch = blockIdx.x & 63;
    int k = bk & 3;
    int b = bk >> 2;
    int d = threadIdx.x;
    int base = ch*CHL;
    {
        const float4* src4 = (const float4*)&g_BC[(bk*LLEN + base)*32];
        float4* dst4 = (float4*)smBC;
        for (int i = d; i < CHL*8; i += 128) dst4[i] = src4[i];
    }
    float a[NN];
    bool fast = true;
#pragma unroll
    for (int n = 0; n < NN; n++) {
        a[n] = -__expf(Alogs[(k*DD + d)*NN + n]);
        fast = fast && (fabsf(a[n] + (float)(n+1)) < 1e-3f);
    }
    float S = 0.f;
    const float* dtp = &g_dtb[(bk*LLEN + base)*DD + d];
    int xrow = (b*2 + (k & 1))*LLEN;
    bool flip = (k >= 2);
    const float* xp;
    int xstep;
    if (!flip) { xp = &g_xsb[(xrow + base)*DD + d]; xstep = DD; }
    else       { xp = &g_xsb[(xrow + (LLEN-1-base))*DD + d]; xstep = -DD; }
    __syncthreads();
    int cb = bk*NCH + ch;
    if (fast) {
        u64 h2[8];
#pragma unroll
        for (int j = 0; j < 8; j++) h2[j] = 0ull;
        float dt_n = dtp[0], x_n = xp[0];
#pragma unroll 2
        for (int s = 0; s < CHL; s++) {
            float dt = dt_n, x = x_n;
            if (s + 1 < CHL) { dt_n = dtp[(s+1)*DD]; x_n = xp[(s+1)*xstep]; }
            float u = dt*x;
            S += dt;
            u64 u2 = pk2(u, u);
            float r = __expf(-dt);
            u64 p2[8];
            pow_tree2(r, p2);
            const ulonglong2* bc2 = (const ulonglong2*)&smBC[s*32];
#pragma unroll
            for (int j = 0; j < 4; j++) {
                ulonglong2 bp = bc2[j];
                h2[2*j]   = fma2(h2[2*j],   p2[2*j],   mul2(u2, bp.x));
                h2[2*j+1] = fma2(h2[2*j+1], p2[2*j+1], mul2(u2, bp.y));
            }
        }
        float q = __expf(-S);
        u64 ap2[8];
        pow_tree2(q, ap2);
#pragma unroll
        for (int j = 0; j < 8; j++) {
            float h0, h1, a0, a1;
            upk2(h2[j], h0, h1);
            upk2(ap2[j], a0, a1);
            g_hend[(cb*NN + 2*j  )*DD + d] = h0;
            g_hend[(cb*NN + 2*j+1)*DD + d] = h1;
            g_ap[(cb*NN + 2*j  )*DD + d] = a0;
            g_ap[(cb*NN + 2*j+1)*DD + d] = a1;
        }
    } else {
        float h[NN];
#pragma unroll
        for (int n = 0; n < NN; n++) h[n] = 0.f;
        for (int s = 0; s < CHL; s++) {
            float dt = dtp[s*DD];
            float x  = xp[s*xstep];
            float u = dt*x;
            S += dt;
            const float* bb = &smBC[s*32];
#pragma unroll
            for (int n = 0; n < NN; n++) h[n] = h[n]*__expf(dt*a[n]) + u*bb[n];
        }
#pragma unroll
        for (int n = 0; n < NN; n++) {
            g_hend[(cb*NN + n)*DD + d] = h[n];
            g_ap[(cb*NN + n)*DD + d] = __expf(a[n]*S);
        }
    }
}

// ---------------- K7: scan phase B (cross-chunk prefix, parallel over n) -----
__global__ void __launch_bounds__(128) k_scanB()
{
    int bk = blockIdx.x >> 4;
    int n  = blockIdx.x & 15;
    int d = threadIdx.x;
    float Hv = 0.f;
    int idx = ((bk*NCH)*NN + n)*DD + d;
    float ap0 = g_ap[idx];
    float he0 = g_hend[idx];
    for (int ch = 0; ch < NCH; ch++) {
        int nidx = idx + NN*DD;
        float ap1 = 0.f, he1 = 0.f;
        if (ch + 1 < NCH) { ap1 = g_ap[nidx]; he1 = g_hend[nidx]; }
        g_H0[idx] = Hv;
        Hv = Hv*ap0 + he0;
        ap0 = ap1; he0 = he1;
        idx = nidx;
    }
}

// ---------------- K8: scan phase C (rescan + y + scatter, packed f32x2) ------
__global__ void __launch_bounds__(128) k_scanC(const float* Alogs, const float* Ds)
{
    __shared__ float smBC[CHL*32];
    int bk = blockIdx.x >> 6;
    int ch = blockIdx.x & 63;
    int k = bk & 3;
    int b = bk >> 2;
    int d = threadIdx.x;
    int base = ch*CHL;
    {
        const float4* src4 = (const float4*)&g_BC[(bk*LLEN + base)*32];
        float4* dst4 = (float4*)smBC;
        for (int i = d; i < CHL*8; i += 128) dst4[i] = src4[i];
    }
    float a[NN];
    bool fast = true;
#pragma unroll
    for (int n = 0; n < NN; n++) {
        a[n] = -__expf(Alogs[(k*DD + d)*NN + n]);
        fast = fast && (fabsf(a[n] + (float)(n+1)) < 1e-3f);
    }
    int cb = bk*NCH + ch;
    float Dv = Ds[k*DD + d];
    const float* dtp = &g_dtb[(bk*LLEN + base)*DD + d];
    int xrow = (b*2 + (k & 1))*LLEN;
    bool flip = (k >= 2);
    const float* xp;
    int xstep;
    if (!flip) { xp = &g_xsb[(xrow + base)*DD + d]; xstep = DD; }
    else       { xp = &g_xsb[(xrow + (LLEN-1-base))*DD + d]; xstep = -DD; }
    float* dst = &g_ysb[k*BKLD + b*LLEN*DD];
    __syncthreads();
    if (fast) {
        u64 h2[8];
#pragma unroll
        for (int j = 0; j < 8; j++)
            h2[j] = pk2(g_H0[(cb*NN + 2*j)*DD + d], g_H0[(cb*NN + 2*j+1)*DD + d]);
        float dt_n = dtp[0], x_n = xp[0];
#pragma unroll 2
        for (int s = 0; s < CHL; s++) {
            float dt = dt_n, x = x_n;
            if (s + 1 < CHL) { dt_n = dtp[(s+1)*DD]; x_n = xp[(s+1)*xstep]; }
            float u = dt*x;
            u64 u2 = pk2(u, u);
            float r = __expf(-dt);
            u64 p2[8];
            pow_tree2(r, p2);
            const ulonglong2* bc2 = (const ulonglong2*)&smBC[s*32];
            u64 ya = 0ull, yb = 0ull;
#pragma unroll
            for (int j = 0; j < 4; j++) {
                ulonglong2 bp = bc2[j];
                ulonglong2 cp = bc2[4 + j];
                h2[2*j]   = fma2(h2[2*j],   p2[2*j],   mul2(u2, bp.x));
                ya = fma2(h2[2*j], cp.x, ya);
                h2[2*j+1] = fma2(h2[2*j+1], p2[2*j+1], mul2(u2, bp.y));
                yb = fma2(h2[2*j+1], cp.y, yb);
            }
            float y0, y1, y2, y3;
            upk2(ya, y0, y1);
            upk2(yb, y2, y3);
            float ys = (y0 + y1) + (y2 + y3) + x*Dv;
            int sa = base + s;
            int lrow;
            if (k == 0)      lrow = sa;
            else if (k == 1) lrow = ((sa & 63) << 6) | (sa >> 6);
            else if (k == 2) lrow = LLEN - 1 - sa;
            else { int m = LLEN - 1 - sa; lrow = ((m & 63) << 6) | (m >> 6); }
            dst[lrow*DD + d] = ys;
        }
    } else {
        float h[NN];
#pragma unroll
        for (int n = 0; n < NN; n++) h[n] = g_H0[(cb*NN + n)*DD + d];
        for (int s = 0; s < CHL; s++) {
            float dt = dtp[s*DD];
            float x  = xp[s*xstep];
            float u = dt*x;
            const float* bb = &smBC[s*32];
            const float* cc = &smBC[s*32 + 16];
            float y0 = 0.f, y1 = 0.f, y2 = 0.f, y3 = 0.f;
#pragma unroll
            for (int n = 0; n < NN; n += 4) {
                h[n+0] = h[n+0]*__expf(dt*a[n+0]) + u*bb[n+0]; y0 += h[n+0]*cc[n+0];
                h[n+1] = h[n+1]*__expf(dt*a[n+1]) + u*bb[n+1]; y1 += h[n+1]*cc[n+1];
                h[n+2] = h[n+2]*__expf(dt*a[n+2]) + u*bb[n+2]; y2 += h[n+2]*cc[n+2];
                h[n+3] = h[n+3]*__expf(dt*a[n+3]) + u*bb[n+3]; y3 += h[n+3]*cc[n+3];
            }
            float ys = (y0 + y1) + (y2 + y3) + x*Dv;
            int sa = base + s;
            int lrow;
            if (k == 0)      lrow = sa;
            else if (k == 1) lrow = ((sa & 63) << 6) | (sa >> 6);
            else if (k == 2) lrow = LLEN - 1 - sa;
            else { int m = LLEN - 1 - sa; lrow = ((m & 63) << 6) | (m >> 6); }
            dst[lrow*DD + d] = ys;
        }
    }
}

// ---------------- K9: combine + LN + gates + out-proj + residual -------------
__global__ void __launch_bounds__(256) k_final(const float* inp, const float* lnw,
                                               const float* lnb, const float* Wout,
                                               float* out)
{
    __shared__ float Wsm[64*132];
    __shared__ float val_sm[8*128];
    __shared__ float osm[64*8];
    int t = threadIdx.x;
    int b = blockIdx.x >> 7;
    int lbase = (blockIdx.x & 127) * 32;
    for (int i = t; i < 64*128; i += 256) {
        int c = i >> 7, dd = i & 127;
        Wsm[c*132 + dd] = Wout[i];
    }
    __syncthreads();
    int w = t >> 5, lane = t & 31;
    float4 lw = ((const float4*)lnw)[lane];
    float4 lb = ((const float4*)lnb)[lane];
    float4 cd = *(const float4*)&g_cond[b*DD + lane*4];
    for (int it = 0; it < 4; it++) {
        int l0 = lbase + it*8;
        int l = l0 + w;
        int off = (b*LLEN + l)*DD + lane*4;
        float4 y4;
        {
            float4 a0 = *(const float4*)&g_ysb[0*BKLD + off];
            float4 a1 = *(const float4*)&g_ysb[1*BKLD + off];
            float4 a2 = *(const float4*)&g_ysb[2*BKLD + off];
            float4 a3 = *(const float4*)&g_ysb[3*BKLD + off];
            y4.x = a0.x + a1.x + a2.x + a3.x;
            y4.y = a0.y + a1.y + a2.y + a3.y;
            y4.z = a0.z + a1.z + a2.z + a3.z;
            y4.w = a0.w + a1.w + a2.w + a3.w;
        }
        float s1 = y4.x + y4.y + y4.z + y4.w;
        float s2 = y4.x*y4.x + y4.y*y4.y + y4.z*y4.z + y4.w*y4.w;
        for (int o2 = 16; o2; o2 >>= 1) {
            s1 += __shfl_xor_sync(0xffffffffu, s1, o2);
            s2 += __shfl_xor_sync(0xffffffffu, s2, o2);
        }
        float mean = s1 * (1.f/128.f);
        float var  = s2 * (1.f/128.f) - mean*mean;
        float rstd = rsqrtf(var + EPSV);
        float4 z4 = *(const float4*)&g_zs[off];
        float4 v4;
        v4.x = ((y4.x - mean)*rstd*lw.x + lb.x) * cd.x * z4.x;
        v4.y = ((y4.y - mean)*rstd*lw.y + lb.y) * cd.y * z4.y;
        v4.z = ((y4.z - mean)*rstd*lw.z + lb.z) * cd.z * z4.z;
        v4.w = ((y4.w - mean)*rstd*lw.w + lb.w) * cd.w * z4.w;
        *(float4*)&val_sm[w*128 + lane*4] = v4;
        __syncwarp();
        float acc0 = 0.f, acc1 = 0.f;
        const float4* vp = (const float4*)&val_sm[w*128];
        const float4* w0 = (const float4*)&Wsm[lane*132];
        const float4* w1 = (const float4*)&Wsm[(lane+32)*132];
#pragma unroll 8
        for (int q = 0; q < 32; q++) {
            float4 v = vp[q];
            float4 wa = w0[q];
            float4 wb = w1[q];
            acc0 += v.x*wa.x + v.y*wa.y + v.z*wa.z + v.w*wa.w;
            acc1 += v.x*wb.x + v.y*wb.y + v.z*wb.z + v.w*wb.w;
        }
        osm[lane*8 + w] = acc0;
        osm[(lane+32)*8 + w] = acc1;
        __syncthreads();
        for (int i = t; i < 64*8; i += 256) {
            int c = i >> 3, li = i & 7;
            int gi = (b*CC + c)*LLEN + l0 + li;
            out[gi] = osm[c*8 + li] + inp[gi]*g_att[b*CC + c];
        }
        __syncthreads();
    }
}

extern "C" void kernel_launch(void* const* d_in, const int* in_sizes, int n_in,
                              void* d_out, int out_size)
{
    const float* inp   = (const float*)d_in[0];
    const float* rep   = (const float*)d_in[1];
    const float* Wg    = (const float*)d_in[2];
    const float* bg    = (const float*)d_in[3];
    const float* Wb    = (const float*)d_in[4];
    const float* bbp   = (const float*)d_in[5];
    const float* Win   = (const float*)d_in[6];
    const float* cw    = (const float*)d_in[7];
    const float* cb    = (const float*)d_in[8];
    const float* xpw   = (const float*)d_in[9];
    const float* dtw   = (const float*)d_in[10];
    const float* dtbp  = (const float*)d_in[11];
    const float* Alogs = (const float*)d_in[12];
    const float* Ds    = (const float*)d_in[13];
    const float* lnw   = (const float*)d_in[14];
    const float* lnb   = (const float*)d_in[15];
    const float* Wc    = (const float*)d_in[16];
    const float* bc    = (const float*)d_in[17];
    const float* Wout  = (const float*)d_in[18];
    const float* Wf1   = (const float*)d_in[19];
    const float* bf1   = (const float*)d_in[20];
    const float* Wf2   = (const float*)d_in[21];
    const float* bf2   = (const float*)d_in[22];
    float* out = (float*)d_out;

    k_small<<<1 + BB*CC, 256>>>(rep, Wg, bg, Wb, bbp, Wc, bc, Wf1, bf1, Wf2, bf2, Win, inp);
    k_inproj<<<BB*128, 256>>>(inp);
    k_conv<<<BB*DD, 256>>>(cw, cb);
    k_xdbl<<<BB*KK*128, 128>>>(xpw, dtw, dtbp);
    k_scanA<<<BB*KK*NCH, 128>>>(Alogs);
    k_scanB<<<BB*KK*NN, 128>>>();
    k_scanC<<<BB*KK*NCH, 128>>>(Alogs, Ds);
    k_final<<<BB*128, 256>>>(inp, lnw, lnb, Wout, out);
}

// round 5
// speedup vs baseline: 1.5541x; 1.0003x over previous
#include <cuda_runtime.h>
#include <math.h>

#define BB 4
#define CC 64
#define HH 64
#define WW 64
#define LLEN 4096
#define RR 64
#define DD 128
#define KK 4
#define NN 16
#define NCH 64
#define CHL 64
#define EPSV 1e-5f
#define BKLD (BB*LLEN*DD)

typedef unsigned long long u64;
typedef unsigned int u32;

__device__ __forceinline__ u64 pk2(float lo, float hi) {
    u64 r; u32 a = __float_as_uint(lo), b = __float_as_uint(hi);
    asm("mov.b64 %0, {%1, %2};" : "=l"(r) : "r"(a), "r"(b));
    return r;
}
__device__ __forceinline__ u64 fma2(u64 a, u64 b, u64 c) {
    u64 d; asm("fma.rn.f32x2 %0, %1, %2, %3;" : "=l"(d) : "l"(a), "l"(b), "l"(c));
    return d;
}
__device__ __forceinline__ u64 mul2(u64 a, u64 b) {
    u64 d; asm("mul.rn.f32x2 %0, %1, %2;" : "=l"(d) : "l"(a), "l"(b));
    return d;
}
__device__ __forceinline__ void upk2(u64 v, float& lo, float& hi) {
    u32 a, b; asm("mov.b64 {%0, %1}, %2;" : "=r"(a), "=r"(b) : "l"(v));
    lo = __uint_as_float(a); hi = __uint_as_float(b);
}
// p2[j] = {r^(2j+1), r^(2j+2)}, dependency depth ~4
__device__ __forceinline__ void pow_tree2(float r, u64* p2) {
    float r2 = r*r, r4 = r2*r2, r8 = r4*r4;
    u64 q0 = pk2(r, r2), s2 = pk2(r2, r2), s4 = pk2(r4, r4), s8 = pk2(r8, r8);
    p2[0] = q0;
    p2[1] = mul2(q0, s2);
    p2[2] = mul2(q0, s4);
    p2[3] = mul2(p2[1], s4);
    p2[4] = mul2(q0, s8);
    p2[5] = mul2(p2[1], s8);
    p2[6] = mul2(p2[2], s8);
    p2[7] = mul2(p2[3], s8);
}

// ---------------- scratch ----------------
__device__ float g_gamma[BB*CC];
__device__ float g_beta[BB*CC];
__device__ float g_cond[BB*DD];
__device__ float g_att[BB*CC];
__device__ float g_mu[BB*CC];
__device__ float g_rstd[BB*CC];
__device__ float g_WinT[CC*2*DD];
__device__ float g_xc[BB*DD*LLEN];
__device__ float g_zs[BB*LLEN*DD];
__device__ float g_xa[BB*DD*LLEN];
__device__ float g_xaT[BB*DD*LLEN];
__device__ float g_xsb[BB*2*LLEN*DD];      // only k=0,1 stored; k>=2 is a flip
__device__ float g_dtb[BB*KK*LLEN*DD];
__device__ float g_BC[BB*KK*LLEN*32];
__device__ float g_hend[BB*KK*NCH*NN*DD];
__device__ float g_ap[BB*KK*NCH*NN*DD];
__device__ float g_H0[BB*KK*NCH*NN*DD];
__device__ float g_ysb[KK*BB*LLEN*DD];

// ---------------- K1: small GEMVs + W_in transpose + IN stats ----------------
__global__ void k_small(const float* rep, const float* Wg, const float* bg,
                        const float* Wb, const float* bb,
                        const float* Wc, const float* bc,
                        const float* Wf1, const float* bf1,
                        const float* Wf2, const float* bf2,
                        const float* Win, const float* inp)
{
    if (blockIdx.x > 0) {       // instance-norm stats, one block per (b,c)
        int bc_i = blockIdx.x - 1;
        int t = threadIdx.x;
        const float* p = inp + bc_i*LLEN;
        float s = 0.f, s2 = 0.f;
        for (int i = t; i < LLEN; i += 256) { float v = p[i]; s += v; s2 += v*v; }
        __shared__ float sh[64];
        for (int off = 16; off; off >>= 1) {
            s  += __shfl_xor_sync(0xffffffffu, s,  off);
            s2 += __shfl_xor_sync(0xffffffffu, s2, off);
        }
        int w = t >> 5, lane = t & 31;
        if (lane == 0) { sh[w] = s; sh[32 + w] = s2; }
        __syncthreads();
        if (t == 0) {
            float S = 0.f, S2 = 0.f;
            for (int i = 0; i < 8; i++) { S += sh[i]; S2 += sh[32 + i]; }
            float mu = S / (float)LLEN;
            float var = S2 / (float)LLEN - mu*mu;
            g_mu[bc_i] = mu;
            g_rstd[bc_i] = rsqrtf(var + EPSV);
        }
        return;
    }
    __shared__ float rs[BB*RR];
    __shared__ float a_sm[BB*16];
    int t = threadIdx.x;
    if (t < BB*RR) rs[t] = rep[t];
    __syncthreads();
    {
        int b = t >> 6, c = t & 63;
        float ag = 0.f, ab = 0.f;
        for (int r = 0; r < RR; r++) {
            float rv = rs[b*RR + r];
            ag += rv * Wg[c*RR + r];
            ab += rv * Wb[c*RR + r];
        }
        g_gamma[t] = ag + bg[c];
        g_beta[t]  = ab + bb[c];
    }
    for (int i = t; i < BB*DD; i += 256) {
        int b = i >> 7, d = i & 127;
        float a = 0.f;
        for (int r = 0; r < RR; r++) a += rs[b*RR + r] * Wc[d*RR + r];
        g_cond[i] = 1.0f + a + bc[d];
    }
    if (t < BB*16) {
        int b = t >> 4, j = t & 15;
        float a = 0.f;
        for (int r = 0; r < RR; r++) a += rs[b*RR + r] * Wf1[j*RR + r];
        a += bf1[j];
        a_sm[t] = a > 0.f ? a : 0.f;
    }
    __syncthreads();
    {
        int b = t >> 6, c = t & 63;
        float s = bf2[c];
        for (int j = 0; j < 16; j++) s += a_sm[b*16 + j] * Wf2[c*16 + j];
        g_att[t] = 1.0f / (1.0f + __expf(-s));
    }
    for (int i = t; i < 2*DD*CC; i += 256) {
        int o = i / CC, c = i - o*CC;
        g_WinT[c*(2*DD) + o] = Win[i];
    }
}

// ---------------- K3: FiLM + in-projection GEMM ----------------
__global__ void __launch_bounds__(256) k_inproj(const float* inp)
{
    __shared__ float buf[256*33];
    int bx = blockIdx.x;
    int b  = bx >> 7;
    int l0 = (bx & 127) * 32;
    int t = threadIdx.x;
    for (int i = t; i < CC*32; i += 256) {
        int c = i >> 5, li = i & 31;
        int bc = b*CC + c;
        float v  = inp[bc*LLEN + l0 + li];
        float sc = g_rstd[bc] * (1.0f + g_gamma[bc]);
        float bi = g_beta[bc] - g_mu[bc]*sc;
        buf[c*36 + li] = v*sc + bi;
    }
    __syncthreads();
    int o = t;
    float acc[32];
#pragma unroll
    for (int li = 0; li < 32; li++) acc[li] = 0.f;
    for (int c = 0; c < CC; c++) {
        float w = g_WinT[c*256 + o];
        const float4* xp = (const float4*)&buf[c*36];
#pragma unroll
        for (int q = 0; q < 8; q++) {
            float4 x4 = xp[q];
            acc[q*4+0] += w*x4.x; acc[q*4+1] += w*x4.y;
            acc[q*4+2] += w*x4.z; acc[q*4+3] += w*x4.w;
        }
    }
    if (o >= DD) {
#pragma unroll
        for (int li = 0; li < 32; li++) {
            float z = acc[li];
            acc[li] = z / (1.0f + __expf(-z));
        }
    }
    __syncthreads();
#pragma unroll
    for (int li = 0; li < 32; li++) buf[o*33 + li] = acc[li];
    __syncthreads();
    for (int i = t; i < DD*32; i += 256) {
        int d = i >> 5, li = i & 31;
        g_xc[(b*DD + d)*LLEN + l0 + li] = buf[d*33 + li];
    }
    for (int i = t; i < DD*32; i += 256) {
        int li = i >> 7, zd = i & 127;
        g_zs[(b*LLEN + l0 + li)*DD + zd] = buf[(128 + zd)*33 + li];
    }
}

// ---------------- K4: depthwise 3x3 conv + silu (+ transpose) ----------------
__global__ void __launch_bounds__(256) k_conv(const float* cw, const float* cb)
{
    int bd = blockIdx.x;
    int d = bd & 127;
    __shared__ float insm[66*66];
    __shared__ float osm[64*65];
    int t = threadIdx.x;
    for (int i = t; i < 66*66; i += 256) insm[i] = 0.f;
    __syncthreads();
    const float* src = &g_xc[bd*LLEN];
    for (int i = t; i < LLEN; i += 256) {
        int h = i >> 6, w = i & 63;
        insm[(h+1)*66 + (w+1)] = src[i];
    }
    float wv[9];
#pragma unroll
    for (int i = 0; i < 9; i++) wv[i] = cw[d*9 + i];
    float bias = cb[d];
    __syncthreads();
    float* dsta = &g_xa[bd*LLEN];
    for (int i = t; i < LLEN; i += 256) {
        int h = i >> 6, w = i & 63;
        float a = bias;
#pragma unroll
        for (int ki = 0; ki < 3; ki++)
#pragma unroll
            for (int kj = 0; kj < 3; kj++)
                a += insm[(h+ki)*66 + (w+kj)] * wv[ki*3+kj];
        float v = a / (1.0f + __expf(-a));
        dsta[i] = v;
        osm[h*65 + w] = v;
    }
    __syncthreads();
    float* dstt = &g_xaT[bd*LLEN];
    for (int i = t; i < LLEN; i += 256) {
        int h = i & 63, w = i >> 6;
        dstt[i] = osm[h*65 + w];
    }
}

// ---------------- K5: x_dbl + dt projection + layout staging ----------------
__global__ void __launch_bounds__(128, 6) k_xdbl(const float* xpw, const float* dtw, const float* dtbp)
{
    __shared__ float xsT[32*132];     // x tile; tail reused as xdbl[36*33] after GEMM
    __shared__ float Wp[36*128];
    int bx = blockIdx.x;
    int b  = bx >> 9;
    int k  = (bx >> 7) & 3;
    int lt = bx & 127;
    int bk = b*KK + k;
    int l0 = lt*32;
    int t = threadIdx.x;
    {   // float4 weight staging
        const float4* wsrc = (const float4*)(xpw + k*36*128);
        float4* wdst = (float4*)Wp;
        for (int i = t; i < 36*32; i += 128) wdst[i] = wsrc[i];
    }
    const float* src = (k & 1) ? &g_xaT[b*DD*LLEN] : &g_xa[b*DD*LLEN];
    bool flip = (k >= 2);
    for (int i = t; i < DD*32; i += 128) {
        int d = i >> 5, li = i & 31;
        int l = l0 + li;
        int m = flip ? (LLEN - 1 - l) : l;
        xsT[li*132 + d] = src[d*LLEN + m];
    }
    __syncthreads();
    if (k < 2) {
        int bk2 = b*2 + k;
        for (int i = t; i < DD*32; i += 128) {
            int li = i >> 7, d = i & 127;
            g_xsb[(bk2*LLEN + l0 + li)*DD + d] = xsT[li*132 + d];
        }
    }
    float acc[9];
    {
        int g = t >> 5, li = t & 31;
#pragma unroll
        for (int r = 0; r < 9; r++) acc[r] = 0.f;
        const float4* xp = (const float4*)&xsT[li*132];
#pragma unroll 2
        for (int d4 = 0; d4 < 32; d4++) {
            float4 x4 = xp[d4];
#pragma unroll
            for (int r = 0; r < 9; r++) {
                float4 w4 = *(const float4*)&Wp[(g*9 + r)*128 + d4*4];
                acc[r] += x4.x*w4.x + x4.y*w4.y + x4.z*w4.z + x4.w*w4.w;
            }
        }
    }
    __syncthreads();          // all xsT reads done; safe to overwrite
    float* xdbl = xsT;        // 36*33 floats reuse
    {
        int g = t >> 5, li = t & 31;
#pragma unroll
        for (int r = 0; r < 9; r++) xdbl[(g*9 + r)*33 + li] = acc[r];
    }
    __syncthreads();
    {
        int d = t;
        float4 w4 = *(const float4*)&dtw[(k*DD + d)*4];
        float bsv = dtbp[k*DD + d];
#pragma unroll 4
        for (int li = 0; li < 32; li++) {
            float s = bsv + xdbl[0*33+li]*w4.x + xdbl[1*33+li]*w4.y
                          + xdbl[2*33+li]*w4.z + xdbl[3*33+li]*w4.w;
            float dt = (s > 20.f) ? s : log1pf(__expf(s));
            g_dtb[(bk*LLEN + l0 + li)*DD + d] = dt;
        }
    }
    for (int i = t; i < 32*32; i += 128) {
        int li = i >> 5, j = i & 31;
        g_BC[(bk*LLEN + l0 + li)*32 + j] = xdbl[(4 + j)*33 + li];
    }
}

// ---------------- K6: scan phase A (per-chunk local scan, packed f32x2) ------
__global__ void __launch_bounds__(128) k_scanA(const float* Alogs)
{
    __shared__ float smBC[CHL*32];
    int bk = blockIdx.x >> 6;
    int ch = blockIdx.x & 63;
    int k = bk & 3;
    int b = bk >> 2;
    int d = threadIdx.x;
    int base = ch*CHL;
    {
        const float4* src4 = (const float4*)&g_BC[(bk*LLEN + base)*32];
        float4* dst4 = (float4*)smBC;
        for (int i = d; i < CHL*8; i += 128) dst4[i] = src4[i];
    }
    float a[NN];
    bool fast = true;
#pragma unroll
    for (int n = 0; n < NN; n++) {
        a[n] = -__expf(Alogs[(k*DD + d)*NN + n]);
        fast = fast && (fabsf(a[n] + (float)(n+1)) < 1e-3f);
    }
    float S = 0.f;
    const float* dtp = &g_dtb[(bk*LLEN + base)*DD + d];
    int xrow = (b*2 + (k & 1))*LLEN;
    bool flip = (k >= 2);
    const float* xp;
    int xstep;
    if (!flip) { xp = &g_xsb[(xrow + base)*DD + d]; xstep = DD; }
    else       { xp = &g_xsb[(xrow + (LLEN-1-base))*DD + d]; xstep = -DD; }
    __syncthreads();
    int cb = bk*NCH + ch;
    if (fast) {
        u64 h2[8];
#pragma unroll
        for (int j = 0; j < 8; j++) h2[j] = 0ull;
        float dt_n = dtp[0], x_n = xp[0];
#pragma unroll 2
        for (int s = 0; s < CHL; s++) {
            float dt = dt_n, x = x_n;
            if (s + 1 < CHL) { dt_n = dtp[(s+1)*DD]; x_n = xp[(s+1)*xstep]; }
            float u = dt*x;
            S += dt;
            u64 u2 = pk2(u, u);
            float r = __expf(-dt);
            u64 p2[8];
            pow_tree2(r, p2);
            const ulonglong2* bc2 = (const ulonglong2*)&smBC[s*32];
#pragma unroll
            for (int j = 0; j < 4; j++) {
                ulonglong2 bp = bc2[j];
                h2[2*j]   = fma2(h2[2*j],   p2[2*j],   mul2(u2, bp.x));
                h2[2*j+1] = fma2(h2[2*j+1], p2[2*j+1], mul2(u2, bp.y));
            }
        }
        float q = __expf(-S);
        u64 ap2[8];
        pow_tree2(q, ap2);
#pragma unroll
        for (int j = 0; j < 8; j++) {
            float h0, h1, a0, a1;
            upk2(h2[j], h0, h1);
            upk2(ap2[j], a0, a1);
            g_hend[(cb*NN + 2*j  )*DD + d] = h0;
            g_hend[(cb*NN + 2*j+1)*DD + d] = h1;
            g_ap[(cb*NN + 2*j  )*DD + d] = a0;
            g_ap[(cb*NN + 2*j+1)*DD + d] = a1;
        }
    } else {
        float h[NN];
#pragma unroll
        for (int n = 0; n < NN; n++) h[n] = 0.f;
        for (int s = 0; s < CHL; s++) {
            float dt = dtp[s*DD];
            float x  = xp[s*xstep];
            float u = dt*x;
            S += dt;
            const float* bb = &smBC[s*32];
#pragma unroll
            for (int n = 0; n < NN; n++) h[n] = h[n]*__expf(dt*a[n]) + u*bb[n];
        }
#pragma unroll
        for (int n = 0; n < NN; n++) {
            g_hend[(cb*NN + n)*DD + d] = h[n];
            g_ap[(cb*NN + n)*DD + d] = __expf(a[n]*S);
        }
    }
}

// ---------------- K7: scan phase B (cross-chunk prefix, MLP=8) ---------------
__global__ void __launch_bounds__(128) k_scanB()
{
    int bk = blockIdx.x >> 4;
    int n  = blockIdx.x & 15;
    int d = threadIdx.x;
    const int stride = NN*DD;
    int base = ((bk*NCH)*NN + n)*DD + d;
    float Hv = 0.f;
    for (int c0 = 0; c0 < NCH; c0 += 8) {
        float ap[8], he[8];
#pragma unroll
        for (int j = 0; j < 8; j++) {
            ap[j] = g_ap[base + (c0+j)*stride];
            he[j] = g_hend[base + (c0+j)*stride];
        }
#pragma unroll
        for (int j = 0; j < 8; j++) {
            g_H0[base + (c0+j)*stride] = Hv;
            Hv = Hv*ap[j] + he[j];
        }
    }
}

// ---------------- K8: scan phase C (rescan + y + scatter, packed f32x2) ------
__global__ void __launch_bounds__(128) k_scanC(const float* Alogs, const float* Ds)
{
    __shared__ float smBC[CHL*32];
    int bk = blockIdx.x >> 6;
    int ch = blockIdx.x & 63;
    int k = bk & 3;
    int b = bk >> 2;
    int d = threadIdx.x;
    int base = ch*CHL;
    {
        const float4* src4 = (const float4*)&g_BC[(bk*LLEN + base)*32];
        float4* dst4 = (float4*)smBC;
        for (int i = d; i < CHL*8; i += 128) dst4[i] = src4[i];
    }
    float a[NN];
    bool fast = true;
#pragma unroll
    for (int n = 0; n < NN; n++) {
        a[n] = -__expf(Alogs[(k*DD + d)*NN + n]);
        fast = fast && (fabsf(a[n] + (float)(n+1)) < 1e-3f);
    }
    int cb = bk*NCH + ch;
    float Dv = Ds[k*DD + d];
    const float* dtp = &g_dtb[(bk*LLEN + base)*DD + d];
    int xrow = (b*2 + (k & 1))*LLEN;
    bool flip = (k >= 2);
    const float* xp;
    int xstep;
    if (!flip) { xp = &g_xsb[(xrow + base)*DD + d]; xstep = DD; }
    else       { xp = &g_xsb[(xrow + (LLEN-1-base))*DD + d]; xstep = -DD; }
    float* dst = &g_ysb[k*BKLD + b*LLEN*DD];
    __syncthreads();
    if (fast) {
        u64 h2[8];
#pragma unroll
        for (int j = 0; j < 8; j++)
            h2[j] = pk2(g_H0[(cb*NN + 2*j)*DD + d], g_H0[(cb*NN + 2*j+1)*DD + d]);
        float dt_n = dtp[0], x_n = xp[0];
#pragma unroll 2
        for (int s = 0; s < CHL; s++) {
            float dt = dt_n, x = x_n;
            if (s + 1 < CHL) { dt_n = dtp[(s+1)*DD]; x_n = xp[(s+1)*xstep]; }
            float u = dt*x;
            u64 u2 = pk2(u, u);
            float r = __expf(-dt);
            u64 p2[8];
            pow_tree2(r, p2);
            const ulonglong2* bc2 = (const ulonglong2*)&smBC[s*32];
            u64 ya = 0ull, yb = 0ull;
#pragma unroll
            for (int j = 0; j < 4; j++) {
                ulonglong2 bp = bc2[j];
                ulonglong2 cp = bc2[4 + j];
                h2[2*j]   = fma2(h2[2*j],   p2[2*j],   mul2(u2, bp.x));
                ya = fma2(h2[2*j], cp.x, ya);
                h2[2*j+1] = fma2(h2[2*j+1], p2[2*j+1], mul2(u2, bp.y));
                yb = fma2(h2[2*j+1], cp.y, yb);
            }
            float y0, y1, y2, y3;
            upk2(ya, y0, y1);
            upk2(yb, y2, y3);
            float ys = (y0 + y1) + (y2 + y3) + x*Dv;
            int sa = base + s;
            int lrow;
            if (k == 0)      lrow = sa;
            else if (k == 1) lrow = ((sa & 63) << 6) | (sa >> 6);
            else if (k == 2) lrow = LLEN - 1 - sa;
            else { int m = LLEN - 1 - sa; lrow = ((m & 63) << 6) | (m >> 6); }
            dst[lrow*DD + d] = ys;
        }
    } else {
        float h[NN];
#pragma unroll
        for (int n = 0; n < NN; n++) h[n] = g_H0[(cb*NN + n)*DD + d];
        for (int s = 0; s < CHL; s++) {
            float dt = dtp[s*DD];
            float x  = xp[s*xstep];
            float u = dt*x;
            const float* bb = &smBC[s*32];
            const float* cc = &smBC[s*32 + 16];
            float y0 = 0.f, y1 = 0.f, y2 = 0.f, y3 = 0.f;
#pragma unroll
            for (int n = 0; n < NN; n += 4) {
                h[n+0] = h[n+0]*__expf(dt*a[n+0]) + u*bb[n+0]; y0 += h[n+0]*cc[n+0];
                h[n+1] = h[n+1]*__expf(dt*a[n+1]) + u*bb[n+1]; y1 += h[n+1]*cc[n+1];
                h[n+2] = h[n+2]*__expf(dt*a[n+2]) + u*bb[n+2]; y2 += h[n+2]*cc[n+2];
                h[n+3] = h[n+3]*__expf(dt*a[n+3]) + u*bb[n+3]; y3 += h[n+3]*cc[n+3];
            }
            float ys = (y0 + y1) + (y2 + y3) + x*Dv;
            int sa = base + s;
            int lrow;
            if (k == 0)      lrow = sa;
            else if (k == 1) lrow = ((sa & 63) << 6) | (sa >> 6);
            else if (k == 2) lrow = LLEN - 1 - sa;
            else { int m = LLEN - 1 - sa; lrow = ((m & 63) << 6) | (m >> 6); }
            dst[lrow*DD + d] = ys;
        }
    }
}

// ---------------- K9: combine + LN + gates + out-proj + residual -------------
__global__ void __launch_bounds__(256) k_final(const float* inp, const float* lnw,
                                               const float* lnb, const float* Wout,
                                               float* out)
{
    __shared__ float Wsm[64*132];
    __shared__ float val_sm[8*128];
    __shared__ float osm[64*8];
    int t = threadIdx.x;
    int b = blockIdx.x >> 7;
    int lbase = (blockIdx.x & 127) * 32;
    for (int i = t; i < 64*32; i += 256) {
        int c = i >> 5, q = i & 31;
        *(float4*)&Wsm[c*132 + q*4] = ((const float4*)Wout)[i];
    }
    __syncthreads();
    int w = t >> 5, lane = t & 31;
    float4 lw = ((const float4*)lnw)[lane];
    float4 lb = ((const float4*)lnb)[lane];
    float4 cd = *(const float4*)&g_cond[b*DD + lane*4];
    for (int it = 0; it < 4; it++) {
        int l0 = lbase + it*8;
        int l = l0 + w;
        int off = (b*LLEN + l)*DD + lane*4;
        float4 y4;
        {
            float4 a0 = *(const float4*)&g_ysb[0*BKLD + off];
            float4 a1 = *(const float4*)&g_ysb[1*BKLD + off];
            float4 a2 = *(const float4*)&g_ysb[2*BKLD + off];
            float4 a3 = *(const float4*)&g_ysb[3*BKLD + off];
            y4.x = a0.x + a1.x + a2.x + a3.x;
            y4.y = a0.y + a1.y + a2.y + a3.y;
            y4.z = a0.z + a1.z + a2.z + a3.z;
            y4.w = a0.w + a1.w + a2.w + a3.w;
        }
        float s1 = y4.x + y4.y + y4.z + y4.w;
        float s2 = y4.x*y4.x + y4.y*y4.y + y4.z*y4.z + y4.w*y4.w;
        for (int o2 = 16; o2; o2 >>= 1) {
            s1 += __shfl_xor_sync(0xffffffffu, s1, o2);
            s2 += __shfl_xor_sync(0xffffffffu, s2, o2);
        }
        float mean = s1 * (1.f/128.f);
        float var  = s2 * (1.f/128.f) - mean*mean;
        float rstd = rsqrtf(var + EPSV);
        float4 z4 = *(const float4*)&g_zs[off];
        float4 v4;
        v4.x = ((y4.x - mean)*rstd*lw.x + lb.x) * cd.x * z4.x;
        v4.y = ((y4.y - mean)*rstd*lw.y + lb.y) * cd.y * z4.y;
        v4.z = ((y4.z - mean)*rstd*lw.z + lb.z) * cd.z * z4.z;
        v4.w = ((y4.w - mean)*rstd*lw.w + lb.w) * cd.w * z4.w;
        *(float4*)&val_sm[w*128 + lane*4] = v4;
        __syncwarp();
        float acc0 = 0.f, acc1 = 0.f;
        const float4* vp = (const float4*)&val_sm[w*128];
        const float4* w0 = (const float4*)&Wsm[lane*132];
        const float4* w1 = (const float4*)&Wsm[(lane+32)*132];
#pragma unroll 8
        for (int q = 0; q < 32; q++) {
            float4 v = vp[q];
            float4 wa = w0[q];
            float4 wb = w1[q];
            acc0 += v.x*wa.x + v.y*wa.y + v.z*wa.z + v.w*wa.w;
            acc1 += v.x*wb.x + v.y*wb.y + v.z*wb.z + v.w*wb.w;
        }
        osm[lane*8 + w] = acc0;
        osm[(lane+32)*8 + w] = acc1;
        __syncthreads();
        for (int i = t; i < 64*8; i += 256) {
            int c = i >> 3, li = i & 7;
            int gi = (b*CC + c)*LLEN + l0 + li;
            out[gi] = osm[c*8 + li] + inp[gi]*g_att[b*CC + c];
        }
        __syncthreads();
    }
}

extern "C" void kernel_launch(void* const* d_in, const int* in_sizes, int n_in,
                              void* d_out, int out_size)
{
    const float* inp   = (const float*)d_in[0];
    const float* rep   = (const float*)d_in[1];
    const float* Wg    = (const float*)d_in[2];
    const float* bg    = (const float*)d_in[3];
    const float* Wb    = (const float*)d_in[4];
    const float* bbp   = (const float*)d_in[5];
    const float* Win   = (const float*)d_in[6];
    const float* cw    = (const float*)d_in[7];
    const float* cb    = (const float*)d_in[8];
    const float* xpw   = (const float*)d_in[9];
    const float* dtw   = (const float*)d_in[10];
    const float* dtbp  = (const float*)d_in[11];
    const float* Alogs = (const float*)d_in[12];
    const float* Ds    = (const float*)d_in[13];
    const float* lnw   = (const float*)d_in[14];
    const float* lnb   = (const float*)d_in[15];
    const float* Wc    = (const float*)d_in[16];
    const float* bc    = (const float*)d_in[17];
    const float* Wout  = (const float*)d_in[18];
    const float* Wf1   = (const float*)d_in[19];
    const float* bf1   = (const float*)d_in[20];
    const float* Wf2   = (const float*)d_in[21];
    const float* bf2   = (const float*)d_in[22];
    float* out = (float*)d_out;

    k_small<<<1 + BB*CC, 256>>>(rep, Wg, bg, Wb, bbp, Wc, bc, Wf1, bf1, Wf2, bf2, Win, inp);
    k_inproj<<<BB*128, 256>>>(inp);
    k_conv<<<BB*DD, 256>>>(cw, cb);
    k_xdbl<<<BB*KK*128, 128>>>(xpw, dtw, dtbp);
    k_scanA<<<BB*KK*NCH, 128>>>(Alogs);
    k_scanB<<<BB*KK*NN, 128>>>();
    k_scanC<<<BB*KK*NCH, 128>>>(Alogs, Ds);
    k_final<<<BB*128, 256>>>(inp, lnw, lnb, Wout, out);
}

// round 6
// speedup vs baseline: 1.5770x; 1.0147x over previous
#include <cuda_runtime.h>
#include <math.h>

#define BB 4
#define CC 64
#define HH 64
#define WW 64
#define LLEN 4096
#define RR 64
#define DD 128
#define KK 4
#define NN 16
#define NCH 64
#define CHL 64
#define EPSV 1e-5f
#define BKLD (BB*LLEN*DD)
#define XDBL_SMEM (64*132 + 36*128)

typedef unsigned long long u64;
typedef unsigned int u32;

__device__ __forceinline__ u64 pk2(float lo, float hi) {
    u64 r; u32 a = __float_as_uint(lo), b = __float_as_uint(hi);
    asm("mov.b64 %0, {%1, %2};" : "=l"(r) : "r"(a), "r"(b));
    return r;
}
__device__ __forceinline__ u64 fma2(u64 a, u64 b, u64 c) {
    u64 d; asm("fma.rn.f32x2 %0, %1, %2, %3;" : "=l"(d) : "l"(a), "l"(b), "l"(c));
    return d;
}
__device__ __forceinline__ u64 mul2(u64 a, u64 b) {
    u64 d; asm("mul.rn.f32x2 %0, %1, %2;" : "=l"(d) : "l"(a), "l"(b));
    return d;
}
__device__ __forceinline__ void upk2(u64 v, float& lo, float& hi) {
    u32 a, b; asm("mov.b64 {%0, %1}, %2;" : "=r"(a), "=r"(b) : "l"(v));
    lo = __uint_as_float(a); hi = __uint_as_float(b);
}
// p2[j] = {r^(2j+1), r^(2j+2)}, dependency depth ~4
__device__ __forceinline__ void pow_tree2(float r, u64* p2) {
    float r2 = r*r, r4 = r2*r2, r8 = r4*r4;
    u64 q0 = pk2(r, r2), s2 = pk2(r2, r2), s4 = pk2(r4, r4), s8 = pk2(r8, r8);
    p2[0] = q0;
    p2[1] = mul2(q0, s2);
    p2[2] = mul2(q0, s4);
    p2[3] = mul2(p2[1], s4);
    p2[4] = mul2(q0, s8);
    p2[5] = mul2(p2[1], s8);
    p2[6] = mul2(p2[2], s8);
    p2[7] = mul2(p2[3], s8);
}
// fast softplus: branch-light, MUFU-based
__device__ __forceinline__ float softplus_f(float s) {
    float as = fabsf(s);
    float sp = fmaxf(s, 0.f) + __logf(1.f + __expf(-as));
    return (s > 20.f) ? s : sp;
}

// ---------------- scratch ----------------
__device__ float g_gamma[BB*CC];
__device__ float g_beta[BB*CC];
__device__ float g_cond[BB*DD];
__device__ float g_att[BB*CC];
__device__ float g_mu[BB*CC];
__device__ float g_rstd[BB*CC];
__device__ float g_WinT[CC*2*DD];
__device__ float g_xc[BB*DD*LLEN];
__device__ float g_zs[BB*LLEN*DD];
__device__ float g_xa[BB*DD*LLEN];
__device__ float g_xaT[BB*DD*LLEN];
__device__ float g_xsb[BB*2*LLEN*DD];      // only k=0,1 stored; k>=2 is a flip
__device__ float g_dtb[BB*KK*LLEN*DD];
__device__ float g_BC[BB*KK*LLEN*32];
__device__ float g_hend[BB*KK*NCH*NN*DD];
__device__ float g_ap[BB*KK*NCH*NN*DD];
__device__ float g_H0[BB*KK*NCH*NN*DD];
__device__ float g_ysb[KK*BB*LLEN*DD];

// ---------------- K1: small GEMVs + W_in transpose + IN stats ----------------
__global__ void k_small(const float* rep, const float* Wg, const float* bg,
                        const float* Wb, const float* bb,
                        const float* Wc, const float* bc,
                        const float* Wf1, const float* bf1,
                        const float* Wf2, const float* bf2,
                        const float* Win, const float* inp)
{
    if (blockIdx.x > 0) {       // instance-norm stats, one block per (b,c)
        int bc_i = blockIdx.x - 1;
        int t = threadIdx.x;
        const float* p = inp + bc_i*LLEN;
        float s = 0.f, s2 = 0.f;
        for (int i = t; i < LLEN; i += 256) { float v = p[i]; s += v; s2 += v*v; }
        __shared__ float sh[64];
        for (int off = 16; off; off >>= 1) {
            s  += __shfl_xor_sync(0xffffffffu, s,  off);
            s2 += __shfl_xor_sync(0xffffffffu, s2, off);
        }
        int w = t >> 5, lane = t & 31;
        if (lane == 0) { sh[w] = s; sh[32 + w] = s2; }
        __syncthreads();
        if (t == 0) {
            float S = 0.f, S2 = 0.f;
            for (int i = 0; i < 8; i++) { S += sh[i]; S2 += sh[32 + i]; }
            float mu = S / (float)LLEN;
            float var = S2 / (float)LLEN - mu*mu;
            g_mu[bc_i] = mu;
            g_rstd[bc_i] = rsqrtf(var + EPSV);
        }
        return;
    }
    __shared__ float rs[BB*RR];
    __shared__ float a_sm[BB*16];
    int t = threadIdx.x;
    if (t < BB*RR) rs[t] = rep[t];
    __syncthreads();
    {
        int b = t >> 6, c = t & 63;
        float ag = 0.f, ab = 0.f;
        for (int r = 0; r < RR; r++) {
            float rv = rs[b*RR + r];
            ag += rv * Wg[c*RR + r];
            ab += rv * Wb[c*RR + r];
        }
        g_gamma[t] = ag + bg[c];
        g_beta[t]  = ab + bb[c];
    }
    for (int i = t; i < BB*DD; i += 256) {
        int b = i >> 7, d = i & 127;
        float a = 0.f;
        for (int r = 0; r < RR; r++) a += rs[b*RR + r] * Wc[d*RR + r];
        g_cond[i] = 1.0f + a + bc[d];
    }
    if (t < BB*16) {
        int b = t >> 4, j = t & 15;
        float a = 0.f;
        for (int r = 0; r < RR; r++) a += rs[b*RR + r] * Wf1[j*RR + r];
        a += bf1[j];
        a_sm[t] = a > 0.f ? a : 0.f;
    }
    __syncthreads();
    {
        int b = t >> 6, c = t & 63;
        float s = bf2[c];
        for (int j = 0; j < 16; j++) s += a_sm[b*16 + j] * Wf2[c*16 + j];
        g_att[t] = 1.0f / (1.0f + __expf(-s));
    }
    for (int i = t; i < 2*DD*CC; i += 256) {
        int o = i / CC, c = i - o*CC;
        g_WinT[c*(2*DD) + o] = Win[i];
    }
}

// ---------------- K3: FiLM + in-projection GEMM ----------------
__global__ void __launch_bounds__(256) k_inproj(const float* inp)
{
    __shared__ float buf[256*33];
    int bx = blockIdx.x;
    int b  = bx >> 7;
    int l0 = (bx & 127) * 32;
    int t = threadIdx.x;
    for (int i = t; i < CC*32; i += 256) {
        int c = i >> 5, li = i & 31;
        int bc = b*CC + c;
        float v  = inp[bc*LLEN + l0 + li];
        float sc = g_rstd[bc] * (1.0f + g_gamma[bc]);
        float bi = g_beta[bc] - g_mu[bc]*sc;
        buf[c*36 + li] = v*sc + bi;
    }
    __syncthreads();
    int o = t;
    float acc[32];
#pragma unroll
    for (int li = 0; li < 32; li++) acc[li] = 0.f;
    for (int c = 0; c < CC; c++) {
        float w = g_WinT[c*256 + o];
        const float4* xp = (const float4*)&buf[c*36];
#pragma unroll
        for (int q = 0; q < 8; q++) {
            float4 x4 = xp[q];
            acc[q*4+0] += w*x4.x; acc[q*4+1] += w*x4.y;
            acc[q*4+2] += w*x4.z; acc[q*4+3] += w*x4.w;
        }
    }
    if (o >= DD) {
#pragma unroll
        for (int li = 0; li < 32; li++) {
            float z = acc[li];
            acc[li] = z / (1.0f + __expf(-z));
        }
    }
    __syncthreads();
#pragma unroll
    for (int li = 0; li < 32; li++) buf[o*33 + li] = acc[li];
    __syncthreads();
    for (int i = t; i < DD*32; i += 256) {
        int d = i >> 5, li = i & 31;
        g_xc[(b*DD + d)*LLEN + l0 + li] = buf[d*33 + li];
    }
    for (int i = t; i < DD*32; i += 256) {
        int li = i >> 7, zd = i & 127;
        g_zs[(b*LLEN + l0 + li)*DD + zd] = buf[(128 + zd)*33 + li];
    }
}

// ---------------- K4: depthwise 3x3 conv + silu (+ transpose) ----------------
__global__ void __launch_bounds__(256) k_conv(const float* cw, const float* cb)
{
    int bd = blockIdx.x;
    int d = bd & 127;
    __shared__ float insm[66*66];
    __shared__ float osm[64*65];
    int t = threadIdx.x;
    // zero only the halo (interior fully overwritten below; disjoint sets, no sync needed between)
    if (t < 66) { insm[t] = 0.f; insm[65*66 + t] = 0.f; }
    if (t < 64) { insm[(t+1)*66] = 0.f; insm[(t+1)*66 + 65] = 0.f; }
    const float* src = &g_xc[bd*LLEN];
    for (int i = t; i < LLEN; i += 256) {
        int h = i >> 6, w = i & 63;
        insm[(h+1)*66 + (w+1)] = src[i];
    }
    float wv[9];
#pragma unroll
    for (int i = 0; i < 9; i++) wv[i] = cw[d*9 + i];
    float bias = cb[d];
    __syncthreads();
    float* dsta = &g_xa[bd*LLEN];
    for (int i = t; i < LLEN; i += 256) {
        int h = i >> 6, w = i & 63;
        float a = bias;
#pragma unroll
        for (int ki = 0; ki < 3; ki++)
#pragma unroll
            for (int kj = 0; kj < 3; kj++)
                a += insm[(h+ki)*66 + (w+kj)] * wv[ki*3+kj];
        float v = a / (1.0f + __expf(-a));
        dsta[i] = v;
        osm[h*65 + w] = v;
    }
    __syncthreads();
    float* dstt = &g_xaT[bd*LLEN];
    for (int i = t; i < LLEN; i += 256) {
        int h = i & 63, w = i >> 6;
        dstt[i] = osm[h*65 + w];
    }
}

// ---------------- K5: x_dbl + dt projection + layout staging (TL=64) ---------
__global__ void __launch_bounds__(128) k_xdbl(const float* xpw, const float* dtw, const float* dtbp)
{
    extern __shared__ float dsm[];
    float* xsT = dsm;                 // [64][132]
    float* Wp  = dsm + 64*132;        // [36][128]
    int bx = blockIdx.x;              // 1024 blocks
    int b  = bx >> 8;
    int k  = (bx >> 6) & 3;
    int lt = bx & 63;
    int bk = b*KK + k;
    int l0 = lt*64;
    int t = threadIdx.x;
    {   // float4 weight staging
        const float4* wsrc = (const float4*)(xpw + k*36*128);
        float4* wdst = (float4*)Wp;
        for (int i = t; i < 36*32; i += 128) wdst[i] = wsrc[i];
    }
    const float* src = (k & 1) ? &g_xaT[b*DD*LLEN] : &g_xa[b*DD*LLEN];
    bool flip = (k >= 2);
    for (int i = t; i < DD*64; i += 128) {      // coalesced over l
        int d = i >> 6, li = i & 63;
        int l = l0 + li;
        int m = flip ? (LLEN - 1 - l) : l;
        xsT[li*132 + d] = src[d*LLEN + m];
    }
    __syncthreads();
    if (k < 2) {
        int bk2 = b*2 + k;
        for (int i = t; i < DD*64; i += 128) {
            int li = i >> 7, d = i & 127;
            g_xsb[(bk2*LLEN + l0 + li)*DD + d] = xsT[li*132 + d];
        }
    }
    float acc[18];
    int g = t >> 5, li = t & 31;
    {
#pragma unroll
        for (int r = 0; r < 18; r++) acc[r] = 0.f;
        const float4* xpa = (const float4*)&xsT[li*132];
        const float4* xpb = (const float4*)&xsT[(li+32)*132];
#pragma unroll 4
        for (int d4 = 0; d4 < 32; d4++) {
            float4 xa = xpa[d4];
            float4 xb = xpb[d4];
#pragma unroll
            for (int r = 0; r < 9; r++) {
                float4 w4 = *(const float4*)&Wp[(g*9 + r)*128 + d4*4];
                acc[r]    += xa.x*w4.x + xa.y*w4.y + xa.z*w4.z + xa.w*w4.w;
                acc[9+r]  += xb.x*w4.x + xb.y*w4.y + xb.z*w4.z + xb.w*w4.w;
            }
        }
    }
    __syncthreads();          // all xsT reads done; safe to overwrite
    float* xdbl = xsT;        // reuse: [36][68]
    {
#pragma unroll
        for (int r = 0; r < 9; r++) {
            xdbl[(g*9 + r)*68 + li]      = acc[r];
            xdbl[(g*9 + r)*68 + li + 32] = acc[9 + r];
        }
    }
    __syncthreads();
    {   // dt projection + softplus -> (bk,l,d)
        int d = t;
        float4 w4 = *(const float4*)&dtw[(k*DD + d)*4];
        float bsv = dtbp[k*DD + d];
#pragma unroll 4
        for (int li2 = 0; li2 < 64; li2++) {
            float s = bsv + xdbl[0*68+li2]*w4.x + xdbl[1*68+li2]*w4.y
                          + xdbl[2*68+li2]*w4.z + xdbl[3*68+li2]*w4.w;
            g_dtb[(bk*LLEN + l0 + li2)*DD + d] = softplus_f(s);
        }
    }
    for (int i = t; i < 32*64; i += 128) {      // B|C -> (bk,l,32)
        int li2 = i >> 5, j = i & 31;
        g_BC[(bk*LLEN + l0 + li2)*32 + j] = xdbl[(4 + j)*68 + li2];
    }
}

// ---------------- K6: scan phase A (per-chunk local scan, packed f32x2) ------
__global__ void __launch_bounds__(128) k_scanA(const float* Alogs)
{
    __shared__ float smBC[CHL*32];
    int bk = blockIdx.x >> 6;
    int ch = blockIdx.x & 63;
    int k = bk & 3;
    int b = bk >> 2;
    int d = threadIdx.x;
    int base = ch*CHL;
    {
        const float4* src4 = (const float4*)&g_BC[(bk*LLEN + base)*32];
        float4* dst4 = (float4*)smBC;
        for (int i = d; i < CHL*8; i += 128) dst4[i] = src4[i];
    }
    float a[NN];
    bool fast = true;
#pragma unroll
    for (int n = 0; n < NN; n++) {
        a[n] = -__expf(Alogs[(k*DD + d)*NN + n]);
        fast = fast && (fabsf(a[n] + (float)(n+1)) < 1e-3f);
    }
    float S = 0.f;
    const float* dtp = &g_dtb[(bk*LLEN + base)*DD + d];
    int xrow = (b*2 + (k & 1))*LLEN;
    bool flip = (k >= 2);
    const float* xp;
    int xstep;
    if (!flip) { xp = &g_xsb[(xrow + base)*DD + d]; xstep = DD; }
    else       { xp = &g_xsb[(xrow + (LLEN-1-base))*DD + d]; xstep = -DD; }
    __syncthreads();
    int cb = bk*NCH + ch;
    if (fast) {
        u64 h2[8];
#pragma unroll
        for (int j = 0; j < 8; j++) h2[j] = 0ull;
        float dt_n = dtp[0], x_n = xp[0];
#pragma unroll 2
        for (int s = 0; s < CHL; s++) {
            float dt = dt_n, x = x_n;
            if (s + 1 < CHL) { dt_n = dtp[(s+1)*DD]; x_n = xp[(s+1)*xstep]; }
            float u = dt*x;
            S += dt;
            u64 u2 = pk2(u, u);
            float r = __expf(-dt);
            u64 p2[8];
            pow_tree2(r, p2);
            const ulonglong2* bc2 = (const ulonglong2*)&smBC[s*32];
#pragma unroll
            for (int j = 0; j < 4; j++) {
                ulonglong2 bp = bc2[j];
                h2[2*j]   = fma2(h2[2*j],   p2[2*j],   mul2(u2, bp.x));
                h2[2*j+1] = fma2(h2[2*j+1], p2[2*j+1], mul2(u2, bp.y));
            }
        }
        float q = __expf(-S);
        u64 ap2[8];
        pow_tree2(q, ap2);
#pragma unroll
        for (int j = 0; j < 8; j++) {
            float h0, h1, a0, a1;
            upk2(h2[j], h0, h1);
            upk2(ap2[j], a0, a1);
            g_hend[(cb*NN + 2*j  )*DD + d] = h0;
            g_hend[(cb*NN + 2*j+1)*DD + d] = h1;
            g_ap[(cb*NN + 2*j  )*DD + d] = a0;
            g_ap[(cb*NN + 2*j+1)*DD + d] = a1;
        }
    } else {
        float h[NN];
#pragma unroll
        for (int n = 0; n < NN; n++) h[n] = 0.f;
        for (int s = 0; s < CHL; s++) {
            float dt = dtp[s*DD];
            float x  = xp[s*xstep];
            float u = dt*x;
            S += dt;
            const float* bb = &smBC[s*32];
#pragma unroll
            for (int n = 0; n < NN; n++) h[n] = h[n]*__expf(dt*a[n]) + u*bb[n];
        }
#pragma unroll
        for (int n = 0; n < NN; n++) {
            g_hend[(cb*NN + n)*DD + d] = h[n];
            g_ap[(cb*NN + n)*DD + d] = __expf(a[n]*S);
        }
    }
}

// ---------------- K7: scan phase B (cross-chunk prefix, MLP=8) ---------------
__global__ void __launch_bounds__(128) k_scanB()
{
    int bk = blockIdx.x >> 4;
    int n  = blockIdx.x & 15;
    int d = threadIdx.x;
    const int stride = NN*DD;
    int base = ((bk*NCH)*NN + n)*DD + d;
    float Hv = 0.f;
    for (int c0 = 0; c0 < NCH; c0 += 8) {
        float ap[8], he[8];
#pragma unroll
        for (int j = 0; j < 8; j++) {
            ap[j] = g_ap[base + (c0+j)*stride];
            he[j] = g_hend[base + (c0+j)*stride];
        }
#pragma unroll
        for (int j = 0; j < 8; j++) {
            g_H0[base + (c0+j)*stride] = Hv;
            Hv = Hv*ap[j] + he[j];
        }
    }
}

// ---------------- K8: scan phase C (rescan + y + scatter, packed f32x2) ------
__global__ void __launch_bounds__(128) k_scanC(const float* Alogs, const float* Ds)
{
    __shared__ float smBC[CHL*32];
    int bk = blockIdx.x >> 6;
    int ch = blockIdx.x & 63;
    int k = bk & 3;
    int b = bk >> 2;
    int d = threadIdx.x;
    int base = ch*CHL;
    {
        const float4* src4 = (const float4*)&g_BC[(bk*LLEN + base)*32];
        float4* dst4 = (float4*)smBC;
        for (int i = d; i < CHL*8; i += 128) dst4[i] = src4[i];
    }
    float a[NN];
    bool fast = true;
#pragma unroll
    for (int n = 0; n < NN; n++) {
        a[n] = -__expf(Alogs[(k*DD + d)*NN + n]);
        fast = fast && (fabsf(a[n] + (float)(n+1)) < 1e-3f);
    }
    int cb = bk*NCH + ch;
    float Dv = Ds[k*DD + d];
    const float* dtp = &g_dtb[(bk*LLEN + base)*DD + d];
    int xrow = (b*2 + (k & 1))*LLEN;
    bool flip = (k >= 2);
    const float* xp;
    int xstep;
    if (!flip) { xp = &g_xsb[(xrow + base)*DD + d]; xstep = DD; }
    else       { xp = &g_xsb[(xrow + (LLEN-1-base))*DD + d]; xstep = -DD; }
    float* dst = &g_ysb[k*BKLD + b*LLEN*DD];
    __syncthreads();
    if (fast) {
        u64 h2[8];
#pragma unroll
        for (int j = 0; j < 8; j++)
            h2[j] = pk2(g_H0[(cb*NN + 2*j)*DD + d], g_H0[(cb*NN + 2*j+1)*DD + d]);
        float dt_n = dtp[0], x_n = xp[0];
#pragma unroll 2
        for (int s = 0; s < CHL; s++) {
            float dt = dt_n, x = x_n;
            if (s + 1 < CHL) { dt_n = dtp[(s+1)*DD]; x_n = xp[(s+1)*xstep]; }
            float u = dt*x;
            u64 u2 = pk2(u, u);
            float r = __expf(-dt);
            u64 p2[8];
            pow_tree2(r, p2);
            const ulonglong2* bc2 = (const ulonglong2*)&smBC[s*32];
            u64 ya = 0ull, yb = 0ull;
#pragma unroll
            for (int j = 0; j < 4; j++) {
                ulonglong2 bp = bc2[j];
                ulonglong2 cp = bc2[4 + j];
                h2[2*j]   = fma2(h2[2*j],   p2[2*j],   mul2(u2, bp.x));
                ya = fma2(h2[2*j], cp.x, ya);
                h2[2*j+1] = fma2(h2[2*j+1], p2[2*j+1], mul2(u2, bp.y));
                yb = fma2(h2[2*j+1], cp.y, yb);
            }
            float y0, y1, y2, y3;
            upk2(ya, y0, y1);
            upk2(yb, y2, y3);
            float ys = (y0 + y1) + (y2 + y3) + x*Dv;
            int sa = base + s;
            int lrow;
            if (k == 0)      lrow = sa;
            else if (k == 1) lrow = ((sa & 63) << 6) | (sa >> 6);
            else if (k == 2) lrow = LLEN - 1 - sa;
            else { int m = LLEN - 1 - sa; lrow = ((m & 63) << 6) | (m >> 6); }
            dst[lrow*DD + d] = ys;
        }
    } else {
        float h[NN];
#pragma unroll
        for (int n = 0; n < NN; n++) h[n] = g_H0[(cb*NN + n)*DD + d];
        for (int s = 0; s < CHL; s++) {
            float dt = dtp[s*DD];
            float x  = xp[s*xstep];
            float u = dt*x;
            const float* bb = &smBC[s*32];
            const float* cc = &smBC[s*32 + 16];
            float y0 = 0.f, y1 = 0.f, y2 = 0.f, y3 = 0.f;
#pragma unroll
            for (int n = 0; n < NN; n += 4) {
                h[n+0] = h[n+0]*__expf(dt*a[n+0]) + u*bb[n+0]; y0 += h[n+0]*cc[n+0];
                h[n+1] = h[n+1]*__expf(dt*a[n+1]) + u*bb[n+1]; y1 += h[n+1]*cc[n+1];
                h[n+2] = h[n+2]*__expf(dt*a[n+2]) + u*bb[n+2]; y2 += h[n+2]*cc[n+2];
                h[n+3] = h[n+3]*__expf(dt*a[n+3]) + u*bb[n+3]; y3 += h[n+3]*cc[n+3];
            }
            float ys = (y0 + y1) + (y2 + y3) + x*Dv;
            int sa = base + s;
            int lrow;
            if (k == 0)      lrow = sa;
            else if (k == 1) lrow = ((sa & 63) << 6) | (sa >> 6);
            else if (k == 2) lrow = LLEN - 1 - sa;
            else { int m = LLEN - 1 - sa; lrow = ((m & 63) << 6) | (m >> 6); }
            dst[lrow*DD + d] = ys;
        }
    }
}

// ---------------- K9: combine + LN + gates + out-proj + residual -------------
__global__ void __launch_bounds__(256) k_final(const float* inp, const float* lnw,
                                               const float* lnb, const float* Wout,
                                               float* out)
{
    __shared__ float Wsm[64*132];
    __shared__ float val_sm[8*128];
    __shared__ float osm[64*8];
    int t = threadIdx.x;
    int b = blockIdx.x >> 7;
    int lbase = (blockIdx.x & 127) * 32;
    for (int i = t; i < 64*32; i += 256) {
        int c = i >> 5, q = i & 31;
        *(float4*)&Wsm[c*132 + q*4] = ((const float4*)Wout)[i];
    }
    __syncthreads();
    int w = t >> 5, lane = t & 31;
    float4 lw = ((const float4*)lnw)[lane];
    float4 lb = ((const float4*)lnb)[lane];
    float4 cd = *(const float4*)&g_cond[b*DD + lane*4];
    for (int it = 0; it < 4; it++) {
        int l0 = lbase + it*8;
        int l = l0 + w;
        int off = (b*LLEN + l)*DD + lane*4;
        float4 y4;
        {
            float4 a0 = *(const float4*)&g_ysb[0*BKLD + off];
            float4 a1 = *(const float4*)&g_ysb[1*BKLD + off];
            float4 a2 = *(const float4*)&g_ysb[2*BKLD + off];
            float4 a3 = *(const float4*)&g_ysb[3*BKLD + off];
            y4.x = a0.x + a1.x + a2.x + a3.x;
            y4.y = a0.y + a1.y + a2.y + a3.y;
            y4.z = a0.z + a1.z + a2.z + a3.z;
            y4.w = a0.w + a1.w + a2.w + a3.w;
        }
        float s1 = y4.x + y4.y + y4.z + y4.w;
        float s2 = y4.x*y4.x + y4.y*y4.y + y4.z*y4.z + y4.w*y4.w;
        for (int o2 = 16; o2; o2 >>= 1) {
            s1 += __shfl_xor_sync(0xffffffffu, s1, o2);
            s2 += __shfl_xor_sync(0xffffffffu, s2, o2);
        }
        float mean = s1 * (1.f/128.f);
        float var  = s2 * (1.f/128.f) - mean*mean;
        float rstd = rsqrtf(var + EPSV);
        float4 z4 = *(const float4*)&g_zs[off];
        float4 v4;
        v4.x = ((y4.x - mean)*rstd*lw.x + lb.x) * cd.x * z4.x;
        v4.y = ((y4.y - mean)*rstd*lw.y + lb.y) * cd.y * z4.y;
        v4.z = ((y4.z - mean)*rstd*lw.z + lb.z) * cd.z * z4.z;
        v4.w = ((y4.w - mean)*rstd*lw.w + lb.w) * cd.w * z4.w;
        *(float4*)&val_sm[w*128 + lane*4] = v4;
        __syncwarp();
        float acc0 = 0.f, acc1 = 0.f;
        const float4* vp = (const float4*)&val_sm[w*128];
        const float4* w0 = (const float4*)&Wsm[lane*132];
        const float4* w1 = (const float4*)&Wsm[(lane+32)*132];
#pragma unroll 8
        for (int q = 0; q < 32; q++) {
            float4 v = vp[q];
            float4 wa = w0[q];
            float4 wb = w1[q];
            acc0 += v.x*wa.x + v.y*wa.y + v.z*wa.z + v.w*wa.w;
            acc1 += v.x*wb.x + v.y*wb.y + v.z*wb.z + v.w*wb.w;
        }
        osm[lane*8 + w] = acc0;
        osm[(lane+32)*8 + w] = acc1;
        __syncthreads();
        for (int i = t; i < 64*8; i += 256) {
            int c = i >> 3, li = i & 7;
            int gi = (b*CC + c)*LLEN + l0 + li;
            out[gi] = osm[c*8 + li] + inp[gi]*g_att[b*CC + c];
        }
        __syncthreads();
    }
}

extern "C" void kernel_launch(void* const* d_in, const int* in_sizes, int n_in,
                              void* d_out, int out_size)
{
    const float* inp   = (const float*)d_in[0];
    const float* rep   = (const float*)d_in[1];
    const float* Wg    = (const float*)d_in[2];
    const float* bg    = (const float*)d_in[3];
    const float* Wb    = (const float*)d_in[4];
    const float* bbp   = (const float*)d_in[5];
    const float* Win   = (const float*)d_in[6];
    const float* cw    = (const float*)d_in[7];
    const float* cb    = (const float*)d_in[8];
    const float* xpw   = (const float*)d_in[9];
    const float* dtw   = (const float*)d_in[10];
    const float* dtbp  = (const float*)d_in[11];
    const float* Alogs = (const float*)d_in[12];
    const float* Ds    = (const float*)d_in[13];
    const float* lnw   = (const float*)d_in[14];
    const float* lnb   = (const float*)d_in[15];
    const float* Wc    = (const float*)d_in[16];
    const float* bc    = (const float*)d_in[17];
    const float* Wout  = (const float*)d_in[18];
    const float* Wf1   = (const float*)d_in[19];
    const float* bf1   = (const float*)d_in[20];
    const float* Wf2   = (const float*)d_in[21];
    const float* bf2   = (const float*)d_in[22];
    float* out = (float*)d_out;

    cudaFuncSetAttribute(k_xdbl, cudaFuncAttributeMaxDynamicSharedMemorySize,
                         XDBL_SMEM * (int)sizeof(float));

    k_small<<<1 + BB*CC, 256>>>(rep, Wg, bg, Wb, bbp, Wc, bc, Wf1, bf1, Wf2, bf2, Win, inp);
    k_inproj<<<BB*128, 256>>>(inp);
    k_conv<<<BB*DD, 256>>>(cw, cb);
    k_xdbl<<<BB*KK*64, 128, XDBL_SMEM * (int)sizeof(float)>>>(xpw, dtw, dtbp);
    k_scanA<<<BB*KK*NCH, 128>>>(Alogs);
    k_scanB<<<BB*KK*NN, 128>>>();
    k_scanC<<<BB*KK*NCH, 128>>>(Alogs, Ds);
    k_final<<<BB*128, 256>>>(inp, lnw, lnb, Wout, out);
}

// round 7
// speedup vs baseline: 1.7949x; 1.1382x over previous
#include <cuda_runtime.h>
#include <math.h>

#define BB 4
#define CC 64
#define HH 64
#define WW 64
#define LLEN 4096
#define RR 64
#define DD 128
#define KK 4
#define NN 16
#define NCH 64
#define CHL 64
#define EPSV 1e-5f
#define BKLD (BB*LLEN*DD)
// smem: xsT [64][132] + W/xdbl/Btr region [36*128]
#define XDBL_SMEM (64*132 + 36*128)

typedef unsigned long long u64;
typedef unsigned int u32;

__device__ __forceinline__ u64 pk2(float lo, float hi) {
    u64 r; u32 a = __float_as_uint(lo), b = __float_as_uint(hi);
    asm("mov.b64 %0, {%1, %2};" : "=l"(r) : "r"(a), "r"(b));
    return r;
}
__device__ __forceinline__ u64 fma2(u64 a, u64 b, u64 c) {
    u64 d; asm("fma.rn.f32x2 %0, %1, %2, %3;" : "=l"(d) : "l"(a), "l"(b), "l"(c));
    return d;
}
__device__ __forceinline__ u64 mul2(u64 a, u64 b) {
    u64 d; asm("mul.rn.f32x2 %0, %1, %2;" : "=l"(d) : "l"(a), "l"(b));
    return d;
}
__device__ __forceinline__ void upk2(u64 v, float& lo, float& hi) {
    u32 a, b; asm("mov.b64 {%0, %1}, %2;" : "=r"(a), "=r"(b) : "l"(v));
    lo = __uint_as_float(a); hi = __uint_as_float(b);
}
// p2[j] = {r^(2j+1), r^(2j+2)}, dependency depth ~4
__device__ __forceinline__ void pow_tree2(float r, u64* p2) {
    float r2 = r*r, r4 = r2*r2, r8 = r4*r4;
    u64 q0 = pk2(r, r2), s2 = pk2(r2, r2), s4 = pk2(r4, r4), s8 = pk2(r8, r8);
    p2[0] = q0;
    p2[1] = mul2(q0, s2);
    p2[2] = mul2(q0, s4);
    p2[3] = mul2(p2[1], s4);
    p2[4] = mul2(q0, s8);
    p2[5] = mul2(p2[1], s8);
    p2[6] = mul2(p2[2], s8);
    p2[7] = mul2(p2[3], s8);
}
// fast softplus: branch-light, MUFU-based
__device__ __forceinline__ float softplus_f(float s) {
    float as = fabsf(s);
    float sp = fmaxf(s, 0.f) + __logf(1.f + __expf(-as));
    return (s > 20.f) ? s : sp;
}

// ---------------- scratch ----------------
__device__ float g_gamma[BB*CC];
__device__ float g_beta[BB*CC];
__device__ float g_cond[BB*DD];
__device__ float g_att[BB*CC];
__device__ float g_mu[BB*CC];
__device__ float g_rstd[BB*CC];
__device__ float g_WinT[CC*2*DD];
__device__ float g_xc[BB*DD*LLEN];
__device__ float g_zs[BB*LLEN*DD];
__device__ float g_xa[BB*DD*LLEN];
__device__ float g_xaT[BB*DD*LLEN];
__device__ float g_xsb[BB*2*LLEN*DD];      // only k=0,1 stored; k>=2 is a flip
__device__ float g_dtb[BB*KK*LLEN*DD];
__device__ float g_BC[BB*KK*LLEN*32];
__device__ float g_hend[BB*KK*NCH*NN*DD];
__device__ float g_ap[BB*KK*NCH*NN*DD];
__device__ float g_H0[BB*KK*NCH*NN*DD];
__device__ float g_ysb[KK*BB*LLEN*DD];

// ---------------- K1: small GEMVs + W_in transpose + IN stats ----------------
__global__ void k_small(const float* rep, const float* Wg, const float* bg,
                        const float* Wb, const float* bb,
                        const float* Wc, const float* bc,
                        const float* Wf1, const float* bf1,
                        const float* Wf2, const float* bf2,
                        const float* Win, const float* inp)
{
    if (blockIdx.x > 0) {       // instance-norm stats, one block per (b,c)
        int bc_i = blockIdx.x - 1;
        int t = threadIdx.x;
        const float* p = inp + bc_i*LLEN;
        float s = 0.f, s2 = 0.f;
        for (int i = t; i < LLEN; i += 256) { float v = p[i]; s += v; s2 += v*v; }
        __shared__ float sh[64];
        for (int off = 16; off; off >>= 1) {
            s  += __shfl_xor_sync(0xffffffffu, s,  off);
            s2 += __shfl_xor_sync(0xffffffffu, s2, off);
        }
        int w = t >> 5, lane = t & 31;
        if (lane == 0) { sh[w] = s; sh[32 + w] = s2; }
        __syncthreads();
        if (t == 0) {
            float S = 0.f, S2 = 0.f;
            for (int i = 0; i < 8; i++) { S += sh[i]; S2 += sh[32 + i]; }
            float mu = S / (float)LLEN;
            float var = S2 / (float)LLEN - mu*mu;
            g_mu[bc_i] = mu;
            g_rstd[bc_i] = rsqrtf(var + EPSV);
        }
        return;
    }
    __shared__ float rs[BB*RR];
    __shared__ float a_sm[BB*16];
    int t = threadIdx.x;
    if (t < BB*RR) rs[t] = rep[t];
    __syncthreads();
    {
        int b = t >> 6, c = t & 63;
        float ag = 0.f, ab = 0.f;
        for (int r = 0; r < RR; r++) {
            float rv = rs[b*RR + r];
            ag += rv * Wg[c*RR + r];
            ab += rv * Wb[c*RR + r];
        }
        g_gamma[t] = ag + bg[c];
        g_beta[t]  = ab + bb[c];
    }
    for (int i = t; i < BB*DD; i += 256) {
        int b = i >> 7, d = i & 127;
        float a = 0.f;
        for (int r = 0; r < RR; r++) a += rs[b*RR + r] * Wc[d*RR + r];
        g_cond[i] = 1.0f + a + bc[d];
    }
    if (t < BB*16) {
        int b = t >> 4, j = t & 15;
        float a = 0.f;
        for (int r = 0; r < RR; r++) a += rs[b*RR + r] * Wf1[j*RR + r];
        a += bf1[j];
        a_sm[t] = a > 0.f ? a : 0.f;
    }
    __syncthreads();
    {
        int b = t >> 6, c = t & 63;
        float s = bf2[c];
        for (int j = 0; j < 16; j++) s += a_sm[b*16 + j] * Wf2[c*16 + j];
        g_att[t] = 1.0f / (1.0f + __expf(-s));
    }
    for (int i = t; i < 2*DD*CC; i += 256) {
        int o = i / CC, c = i - o*CC;
        g_WinT[c*(2*DD) + o] = Win[i];
    }
}

// ---------------- K3: FiLM + in-projection GEMM ----------------
__global__ void __launch_bounds__(256) k_inproj(const float* inp)
{
    __shared__ float buf[256*33];
    int bx = blockIdx.x;
    int b  = bx >> 7;
    int l0 = (bx & 127) * 32;
    int t = threadIdx.x;
    for (int i = t; i < CC*32; i += 256) {
        int c = i >> 5, li = i & 31;
        int bc = b*CC + c;
        float v  = inp[bc*LLEN + l0 + li];
        float sc = g_rstd[bc] * (1.0f + g_gamma[bc]);
        float bi = g_beta[bc] - g_mu[bc]*sc;
        buf[c*36 + li] = v*sc + bi;
    }
    __syncthreads();
    int o = t;
    float acc[32];
#pragma unroll
    for (int li = 0; li < 32; li++) acc[li] = 0.f;
    for (int c = 0; c < CC; c++) {
        float w = g_WinT[c*256 + o];
        const float4* xp = (const float4*)&buf[c*36];
#pragma unroll
        for (int q = 0; q < 8; q++) {
            float4 x4 = xp[q];
            acc[q*4+0] += w*x4.x; acc[q*4+1] += w*x4.y;
            acc[q*4+2] += w*x4.z; acc[q*4+3] += w*x4.w;
        }
    }
    if (o >= DD) {
#pragma unroll
        for (int li = 0; li < 32; li++) {
            float z = acc[li];
            acc[li] = z / (1.0f + __expf(-z));
        }
    }
    __syncthreads();
#pragma unroll
    for (int li = 0; li < 32; li++) buf[o*33 + li] = acc[li];
    __syncthreads();
    for (int i = t; i < DD*32; i += 256) {
        int d = i >> 5, li = i & 31;
        g_xc[(b*DD + d)*LLEN + l0 + li] = buf[d*33 + li];
    }
    for (int i = t; i < DD*32; i += 256) {
        int li = i >> 7, zd = i & 127;
        g_zs[(b*LLEN + l0 + li)*DD + zd] = buf[(128 + zd)*33 + li];
    }
}

// ---------------- K4: depthwise 3x3 conv + silu (+ transpose) ----------------
__global__ void __launch_bounds__(256) k_conv(const float* cw, const float* cb)
{
    int bd = blockIdx.x;
    int d = bd & 127;
    __shared__ float insm[66*66];
    __shared__ float osm[64*65];
    int t = threadIdx.x;
    if (t < 66) { insm[t] = 0.f; insm[65*66 + t] = 0.f; }
    if (t < 64) { insm[(t+1)*66] = 0.f; insm[(t+1)*66 + 65] = 0.f; }
    const float* src = &g_xc[bd*LLEN];
    for (int i = t; i < LLEN; i += 256) {
        int h = i >> 6, w = i & 63;
        insm[(h+1)*66 + (w+1)] = src[i];
    }
    float wv[9];
#pragma unroll
    for (int i = 0; i < 9; i++) wv[i] = cw[d*9 + i];
    float bias = cb[d];
    __syncthreads();
    float* dsta = &g_xa[bd*LLEN];
    for (int i = t; i < LLEN; i += 256) {
        int h = i >> 6, w = i & 63;
        float a = bias;
#pragma unroll
        for (int ki = 0; ki < 3; ki++)
#pragma unroll
            for (int kj = 0; kj < 3; kj++)
                a += insm[(h+ki)*66 + (w+kj)] * wv[ki*3+kj];
        float v = a / (1.0f + __expf(-a));
        dsta[i] = v;
        osm[h*65 + w] = v;
    }
    __syncthreads();
    float* dstt = &g_xaT[bd*LLEN];
    for (int i = t; i < LLEN; i += 256) {
        int h = i & 63, w = i >> 6;
        dstt[i] = osm[h*65 + w];
    }
}

// ---- K5: x_dbl GEMM + dt-proj + FUSED chunk-local scan (phase A) ------------
__global__ void __launch_bounds__(128) k_xdbl(const float* xpw, const float* dtw,
                                              const float* dtbp, const float* Alogs)
{
    extern __shared__ float dsm[];
    float* xsT = dsm;                 // [64][132], live through the scan
    float* Wp  = dsm + 64*132;        // [36][128]; dead after GEMM -> reused:
    float* xdbl = Wp;                 //   [36][68]  (2448 floats)
    float* Btr  = Wp + 2448;          //   [64][24]: cols 0-15 = B, 16-19 = dt-rank rows
    int bx = blockIdx.x;              // 1024 blocks
    int b  = bx >> 8;
    int k  = (bx >> 6) & 3;
    int lt = bx & 63;                 // == scan chunk index
    int bk = b*KK + k;
    int l0 = lt*64;
    int t = threadIdx.x;
    {   // float4 weight staging
        const float4* wsrc = (const float4*)(xpw + k*36*128);
        float4* wdst = (float4*)Wp;
        for (int i = t; i < 36*32; i += 128) wdst[i] = wsrc[i];
    }
    const float* src = (k & 1) ? &g_xaT[b*DD*LLEN] : &g_xa[b*DD*LLEN];
    bool flip = (k >= 2);
    for (int i = t; i < DD*64; i += 128) {      // coalesced over l
        int d = i >> 6, li = i & 63;
        int l = l0 + li;
        int m = flip ? (LLEN - 1 - l) : l;
        xsT[li*132 + d] = src[d*LLEN + m];
    }
    __syncthreads();
    if (k < 2) {
        int bk2 = b*2 + k;
        for (int i = t; i < DD*64; i += 128) {
            int li = i >> 7, d = i & 127;
            g_xsb[(bk2*LLEN + l0 + li)*DD + d] = xsT[li*132 + d];
        }
    }
    float acc[18];
    int g = t >> 5, li = t & 31;
    {
#pragma unroll
        for (int r = 0; r < 18; r++) acc[r] = 0.f;
        const float4* xpa = (const float4*)&xsT[li*132];
        const float4* xpb = (const float4*)&xsT[(li+32)*132];
#pragma unroll 4
        for (int d4 = 0; d4 < 32; d4++) {
            float4 xa = xpa[d4];
            float4 xb = xpb[d4];
#pragma unroll
            for (int r = 0; r < 9; r++) {
                float4 w4 = *(const float4*)&Wp[(g*9 + r)*128 + d4*4];
                acc[r]    += xa.x*w4.x + xa.y*w4.y + xa.z*w4.z + xa.w*w4.w;
                acc[9+r]  += xb.x*w4.x + xb.y*w4.y + xb.z*w4.z + xb.w*w4.w;
            }
        }
    }
    __syncthreads();          // all Wp reads done; safe to overwrite with xdbl
    {
#pragma unroll
        for (int r = 0; r < 9; r++) {
            xdbl[(g*9 + r)*68 + li]      = acc[r];
            xdbl[(g*9 + r)*68 + li + 32] = acc[9 + r];
        }
    }
    __syncthreads();
    // stage B-rows + dt-rank rows transposed into Btr; write g_BC
    for (int i = t; i < 64*16; i += 128) {      // B
        int li2 = i >> 4, n = i & 15;
        Btr[li2*24 + n] = xdbl[(4 + n)*68 + li2];
    }
    for (int i = t; i < 64*4; i += 128) {       // dt-rank rows
        int li2 = i >> 2, r = i & 3;
        Btr[li2*24 + 16 + r] = xdbl[r*68 + li2];
    }
    for (int i = t; i < 32*64; i += 128) {      // B|C -> (bk,l,32) for scanC
        int li2 = i >> 5, j = i & 31;
        g_BC[(bk*LLEN + l0 + li2)*32 + j] = xdbl[(4 + j)*68 + li2];
    }
    __syncthreads();
    // ---- fused chunk-local scan (phase A) + dt store ----
    int d = t;
    float a[NN];
    bool fast = true;
#pragma unroll
    for (int n = 0; n < NN; n++) {
        a[n] = -__expf(Alogs[(k*DD + d)*NN + n]);
        fast = fast && (fabsf(a[n] + (float)(n+1)) < 1e-3f);
    }
    float4 w4 = *(const float4*)&dtw[(k*DD + d)*4];
    float bsv = dtbp[k*DD + d];
    float* dtdst = &g_dtb[(bk*LLEN + l0)*DD + d];
    float S = 0.f;
    int cb = bk*NCH + lt;
    if (fast) {
        u64 h2[8];
#pragma unroll
        for (int j = 0; j < 8; j++) h2[j] = 0ull;
#pragma unroll 2
        for (int s = 0; s < CHL; s++) {
            float4 dr = *(const float4*)&Btr[s*24 + 16];
            float sv = bsv + dr.x*w4.x + dr.y*w4.y + dr.z*w4.z + dr.w*w4.w;
            float dt = softplus_f(sv);
            dtdst[s*DD] = dt;
            float x = xsT[s*132 + d];
            float u = dt*x;
            S += dt;
            u64 u2 = pk2(u, u);
            float r = __expf(-dt);
            u64 p2[8];
            pow_tree2(r, p2);
            const ulonglong2* bc2 = (const ulonglong2*)&Btr[s*24];
#pragma unroll
            for (int j = 0; j < 4; j++) {
                ulonglong2 bp = bc2[j];
                h2[2*j]   = fma2(h2[2*j],   p2[2*j],   mul2(u2, bp.x));
                h2[2*j+1] = fma2(h2[2*j+1], p2[2*j+1], mul2(u2, bp.y));
            }
        }
        float q = __expf(-S);
        u64 ap2[8];
        pow_tree2(q, ap2);
#pragma unroll
        for (int j = 0; j < 8; j++) {
            float h0, h1, a0, a1;
            upk2(h2[j], h0, h1);
            upk2(ap2[j], a0, a1);
            g_hend[(cb*NN + 2*j  )*DD + d] = h0;
            g_hend[(cb*NN + 2*j+1)*DD + d] = h1;
            g_ap[(cb*NN + 2*j  )*DD + d] = a0;
            g_ap[(cb*NN + 2*j+1)*DD + d] = a1;
        }
    } else {
        float h[NN];
#pragma unroll
        for (int n = 0; n < NN; n++) h[n] = 0.f;
        for (int s = 0; s < CHL; s++) {
            float4 dr = *(const float4*)&Btr[s*24 + 16];
            float sv = bsv + dr.x*w4.x + dr.y*w4.y + dr.z*w4.z + dr.w*w4.w;
            float dt = softplus_f(sv);
            dtdst[s*DD] = dt;
            float x = xsT[s*132 + d];
            float u = dt*x;
            S += dt;
            const float* bb = &Btr[s*24];
#pragma unroll
            for (int n = 0; n < NN; n++) h[n] = h[n]*__expf(dt*a[n]) + u*bb[n];
        }
#pragma unroll
        for (int n = 0; n < NN; n++) {
            g_hend[(cb*NN + n)*DD + d] = h[n];
            g_ap[(cb*NN + n)*DD + d] = __expf(a[n]*S);
        }
    }
}

// ---------------- K7: scan phase B (cross-chunk prefix, MLP=8) ---------------
__global__ void __launch_bounds__(128) k_scanB()
{
    int bk = blockIdx.x >> 4;
    int n  = blockIdx.x & 15;
    int d = threadIdx.x;
    const int stride = NN*DD;
    int base = ((bk*NCH)*NN + n)*DD + d;
    float Hv = 0.f;
    for (int c0 = 0; c0 < NCH; c0 += 8) {
        float ap[8], he[8];
#pragma unroll
        for (int j = 0; j < 8; j++) {
            ap[j] = g_ap[base + (c0+j)*stride];
            he[j] = g_hend[base + (c0+j)*stride];
        }
#pragma unroll
        for (int j = 0; j < 8; j++) {
            g_H0[base + (c0+j)*stride] = Hv;
            Hv = Hv*ap[j] + he[j];
        }
    }
}

// ---------------- K8: scan phase C (rescan + y + scatter, packed f32x2) ------
__global__ void __launch_bounds__(128) k_scanC(const float* Alogs, const float* Ds)
{
    __shared__ float smBC[CHL*32];
    int bk = blockIdx.x >> 6;
    int ch = blockIdx.x & 63;
    int k = bk & 3;
    int b = bk >> 2;
    int d = threadIdx.x;
    int base = ch*CHL;
    {
        const float4* src4 = (const float4*)&g_BC[(bk*LLEN + base)*32];
        float4* dst4 = (float4*)smBC;
        for (int i = d; i < CHL*8; i += 128) dst4[i] = src4[i];
    }
    float a[NN];
    bool fast = true;
#pragma unroll
    for (int n = 0; n < NN; n++) {
        a[n] = -__expf(Alogs[(k*DD + d)*NN + n]);
        fast = fast && (fabsf(a[n] + (float)(n+1)) < 1e-3f);
    }
    int cb = bk*NCH + ch;
    float Dv = Ds[k*DD + d];
    const float* dtp = &g_dtb[(bk*LLEN + base)*DD + d];
    int xrow = (b*2 + (k & 1))*LLEN;
    bool flip = (k >= 2);
    const float* xp;
    int xstep;
    if (!flip) { xp = &g_xsb[(xrow + base)*DD + d]; xstep = DD; }
    else       { xp = &g_xsb[(xrow + (LLEN-1-base))*DD + d]; xstep = -DD; }
    float* dst = &g_ysb[k*BKLD + b*LLEN*DD];
    __syncthreads();
    if (fast) {
        u64 h2[8];
#pragma unroll
        for (int j = 0; j < 8; j++)
            h2[j] = pk2(g_H0[(cb*NN + 2*j)*DD + d], g_H0[(cb*NN + 2*j+1)*DD + d]);
        float dt_n = dtp[0], x_n = xp[0];
#pragma unroll 2
        for (int s = 0; s < CHL; s++) {
            float dt = dt_n, x = x_n;
            if (s + 1 < CHL) { dt_n = dtp[(s+1)*DD]; x_n = xp[(s+1)*xstep]; }
            float u = dt*x;
            u64 u2 = pk2(u, u);
            float r = __expf(-dt);
            u64 p2[8];
            pow_tree2(r, p2);
            const ulonglong2* bc2 = (const ulonglong2*)&smBC[s*32];
            u64 ya = 0ull, yb = 0ull;
#pragma unroll
            for (int j = 0; j < 4; j++) {
                ulonglong2 bp = bc2[j];
                ulonglong2 cp = bc2[4 + j];
                h2[2*j]   = fma2(h2[2*j],   p2[2*j],   mul2(u2, bp.x));
                ya = fma2(h2[2*j], cp.x, ya);
                h2[2*j+1] = fma2(h2[2*j+1], p2[2*j+1], mul2(u2, bp.y));
                yb = fma2(h2[2*j+1], cp.y, yb);
            }
            float y0, y1, y2, y3;
            upk2(ya, y0, y1);
            upk2(yb, y2, y3);
            float ys = (y0 + y1) + (y2 + y3) + x*Dv;
            int sa = base + s;
            int lrow;
            if (k == 0)      lrow = sa;
            else if (k == 1) lrow = ((sa & 63) << 6) | (sa >> 6);
            else if (k == 2) lrow = LLEN - 1 - sa;
            else { int m = LLEN - 1 - sa; lrow = ((m & 63) << 6) | (m >> 6); }
            dst[lrow*DD + d] = ys;
        }
    } else {
        float h[NN];
#pragma unroll
        for (int n = 0; n < NN; n++) h[n] = g_H0[(cb*NN + n)*DD + d];
        for (int s = 0; s < CHL; s++) {
            float dt = dtp[s*DD];
            float x  = xp[s*xstep];
            float u = dt*x;
            const float* bb = &smBC[s*32];
            const float* cc = &smBC[s*32 + 16];
            float y0 = 0.f, y1 = 0.f, y2 = 0.f, y3 = 0.f;
#pragma unroll
            for (int n = 0; n < NN; n += 4) {
                h[n+0] = h[n+0]*__expf(dt*a[n+0]) + u*bb[n+0]; y0 += h[n+0]*cc[n+0];
                h[n+1] = h[n+1]*__expf(dt*a[n+1]) + u*bb[n+1]; y1 += h[n+1]*cc[n+1];
                h[n+2] = h[n+2]*__expf(dt*a[n+2]) + u*bb[n+2]; y2 += h[n+2]*cc[n+2];
                h[n+3] = h[n+3]*__expf(dt*a[n+3]) + u*bb[n+3]; y3 += h[n+3]*cc[n+3];
            }
            float ys = (y0 + y1) + (y2 + y3) + x*Dv;
            int sa = base + s;
            int lrow;
            if (k == 0)      lrow = sa;
            else if (k == 1) lrow = ((sa & 63) << 6) | (sa >> 6);
            else if (k == 2) lrow = LLEN - 1 - sa;
            else { int m = LLEN - 1 - sa; lrow = ((m & 63) << 6) | (m >> 6); }
            dst[lrow*DD + d] = ys;
        }
    }
}

// ---------------- K9: combine + LN + gates + out-proj + residual -------------
__global__ void __launch_bounds__(256) k_final(const float* inp, const float* lnw,
                                               const float* lnb, const float* Wout,
                                               float* out)
{
    __shared__ float Wsm[64*132];
    __shared__ float val_sm[8*128];
    __shared__ float osm[64*8];
    int t = threadIdx.x;
    int b = blockIdx.x >> 7;
    int lbase = (blockIdx.x & 127) * 32;
    for (int i = t; i < 64*32; i += 256) {
        int c = i >> 5, q = i & 31;
        *(float4*)&Wsm[c*132 + q*4] = ((const float4*)Wout)[i];
    }
    __syncthreads();
    int w = t >> 5, lane = t & 31;
    float4 lw = ((const float4*)lnw)[lane];
    float4 lb = ((const float4*)lnb)[lane];
    float4 cd = *(const float4*)&g_cond[b*DD + lane*4];
    for (int it = 0; it < 4; it++) {
        int l0 = lbase + it*8;
        int l = l0 + w;
        int off = (b*LLEN + l)*DD + lane*4;
        float4 y4;
        {
            float4 a0 = *(const float4*)&g_ysb[0*BKLD + off];
            float4 a1 = *(const float4*)&g_ysb[1*BKLD + off];
            float4 a2 = *(const float4*)&g_ysb[2*BKLD + off];
            float4 a3 = *(const float4*)&g_ysb[3*BKLD + off];
            y4.x = a0.x + a1.x + a2.x + a3.x;
            y4.y = a0.y + a1.y + a2.y + a3.y;
            y4.z = a0.z + a1.z + a2.z + a3.z;
            y4.w = a0.w + a1.w + a2.w + a3.w;
        }
        float s1 = y4.x + y4.y + y4.z + y4.w;
        float s2 = y4.x*y4.x + y4.y*y4.y + y4.z*y4.z + y4.w*y4.w;
        for (int o2 = 16; o2; o2 >>= 1) {
            s1 += __shfl_xor_sync(0xffffffffu, s1, o2);
            s2 += __shfl_xor_sync(0xffffffffu, s2, o2);
        }
        float mean = s1 * (1.f/128.f);
        float var  = s2 * (1.f/128.f) - mean*mean;
        float rstd = rsqrtf(var + EPSV);
        float4 z4 = *(const float4*)&g_zs[off];
        float4 v4;
        v4.x = ((y4.x - mean)*rstd*lw.x + lb.x) * cd.x * z4.x;
        v4.y = ((y4.y - mean)*rstd*lw.y + lb.y) * cd.y * z4.y;
        v4.z = ((y4.z - mean)*rstd*lw.z + lb.z) * cd.z * z4.z;
        v4.w = ((y4.w - mean)*rstd*lw.w + lb.w) * cd.w * z4.w;
        *(float4*)&val_sm[w*128 + lane*4] = v4;
        __syncwarp();
        float acc0 = 0.f, acc1 = 0.f;
        const float4* vp = (const float4*)&val_sm[w*128];
        const float4* w0 = (const float4*)&Wsm[lane*132];
        const float4* w1 = (const float4*)&Wsm[(lane+32)*132];
#pragma unroll 8
        for (int q = 0; q < 32; q++) {
            float4 v = vp[q];
            float4 wa = w0[q];
            float4 wb = w1[q];
            acc0 += v.x*wa.x + v.y*wa.y + v.z*wa.z + v.w*wa.w;
            acc1 += v.x*wb.x + v.y*wb.y + v.z*wb.z + v.w*wb.w;
        }
        osm[lane*8 + w] = acc0;
        osm[(lane+32)*8 + w] = acc1;
        __syncthreads();
        for (int i = t; i < 64*8; i += 256) {
            int c = i >> 3, li = i & 7;
            int gi = (b*CC + c)*LLEN + l0 + li;
            out[gi] = osm[c*8 + li] + inp[gi]*g_att[b*CC + c];
        }
        __syncthreads();
    }
}

extern "C" void kernel_launch(void* const* d_in, const int* in_sizes, int n_in,
                              void* d_out, int out_size)
{
    const float* inp   = (const float*)d_in[0];
    const float* rep   = (const float*)d_in[1];
    const float* Wg    = (const float*)d_in[2];
    const float* bg    = (const float*)d_in[3];
    const float* Wb    = (const float*)d_in[4];
    const float* bbp   = (const float*)d_in[5];
    const float* Win   = (const float*)d_in[6];
    const float* cw    = (const float*)d_in[7];
    const float* cb    = (const float*)d_in[8];
    const float* xpw   = (const float*)d_in[9];
    const float* dtw   = (const float*)d_in[10];
    const float* dtbp  = (const float*)d_in[11];
    const float* Alogs = (const float*)d_in[12];
    const float* Ds    = (const float*)d_in[13];
    const float* lnw   = (const float*)d_in[14];
    const float* lnb   = (const float*)d_in[15];
    const float* Wc    = (const float*)d_in[16];
    const float* bc    = (const float*)d_in[17];
    const float* Wout  = (const float*)d_in[18];
    const float* Wf1   = (const float*)d_in[19];
    const float* bf1   = (const float*)d_in[20];
    const float* Wf2   = (const float*)d_in[21];
    const float* bf2   = (const float*)d_in[22];
    float* out = (float*)d_out;

    cudaFuncSetAttribute(k_xdbl, cudaFuncAttributeMaxDynamicSharedMemorySize,
                         XDBL_SMEM * (int)sizeof(float));

    k_small<<<1 + BB*CC, 256>>>(rep, Wg, bg, Wb, bbp, Wc, bc, Wf1, bf1, Wf2, bf2, Win, inp);
    k_inproj<<<BB*128, 256>>>(inp);
    k_conv<<<BB*DD, 256>>>(cw, cb);
    k_xdbl<<<BB*KK*64, 128, XDBL_SMEM * (int)sizeof(float)>>>(xpw, dtw, dtbp, Alogs);
    k_scanB<<<BB*KK*NN, 128>>>();
    k_scanC<<<BB*KK*NCH, 128>>>(Alogs, Ds);
    k_final<<<BB*128, 256>>>(inp, lnw, lnb, Wout, out);
}